// round 8
// baseline (speedup 1.0000x reference)
#include <cuda_runtime.h>
#include <cuda_fp16.h>
#include <math.h>
#include <cstdint>
#include <cstddef>

#define B_   8
#define N_   2048
#define F_   256
#define TM   64
#define TK   32
#define ALPHA 0.2f
#define WSCALE 0.00390625f     // 2^-8, cancels in softmax ratio

// ---------------- device scratch (allocation-free rule) ----------------
__device__ float g_s1[B_ * N_];
__device__ float g_s2[B_ * N_];
__device__ __half g_WhT_hi[B_ * F_ * N_];   // [b][f][j]
__device__ __half g_WhT_lo[B_ * F_ * N_];

__device__ __forceinline__ uint32_t smem_u32(const void* p) {
    uint32_t a;
    asm("{ .reg .u64 t; cvta.to.shared.u64 t, %1; cvt.u32.u64 %0, t; }"
        : "=r"(a) : "l"(p));
    return a;
}
__device__ __forceinline__ void ldm_x4(uint32_t& r0, uint32_t& r1,
                                       uint32_t& r2, uint32_t& r3, uint32_t addr) {
    asm volatile("ldmatrix.sync.aligned.m8n8.x4.shared.b16 {%0,%1,%2,%3}, [%4];"
                 : "=r"(r0), "=r"(r1), "=r"(r2), "=r"(r3) : "r"(addr));
}
__device__ __forceinline__ void mma_f16(float* d, const uint32_t* a,
                                        uint32_t b0, uint32_t b1) {
    asm volatile(
        "mma.sync.aligned.m16n8k16.row.col.f32.f16.f16.f32 "
        "{%0,%1,%2,%3}, {%4,%5,%6,%7}, {%8,%9}, {%0,%1,%2,%3};"
        : "+f"(d[0]), "+f"(d[1]), "+f"(d[2]), "+f"(d[3])
        : "r"(a[0]), "r"(a[1]), "r"(a[2]), "r"(a[3]), "r"(b0), "r"(b1));
}
__device__ __forceinline__ void cp_async16(uint32_t dst, const void* src) {
    asm volatile("cp.async.cg.shared.global [%0], [%1], 16;"
                 :: "r"(dst), "l"(src) : "memory");
}
#define CP_COMMIT() asm volatile("cp.async.commit_group;" ::: "memory")
#define CP_WAIT0()  asm volatile("cp.async.wait_group 0;" ::: "memory")

// w-pair: leaky+exp+mask (scaled by 2^-8), fp16 pack, scaled rowsum accumulate
__device__ __forceinline__ void make_w_pair(float s1v, int a0, int a1,
                                            float s20, float s21,
                                            float& lsum, uint32_t& hiP)
{
    float x0 = s1v + s20; x0 = fmaxf(x0, ALPHA * x0);
    float x1 = s1v + s21; x1 = fmaxf(x1, ALPHA * x1);
    float w0 = (a0 > 0) ? __expf(x0) * WSCALE : 0.f;
    float w1 = (a1 > 0) ? __expf(x1) * WSCALE : 0.f;
    lsum += w0 + w1;
    __half2 hp = __floats2half2_rn(w0, w1);
    hiP = *(uint32_t*)&hp;
}

// ---------------------------------------------------------------------------
// Kernel 1: Wh = h @ W^T + b ; emits WhT hi/lo (fp16 split, [b][f][j]) + s1/s2
// ---------------------------------------------------------------------------
__global__ void __launch_bounds__(256) k1_gemm(
    const float* __restrict__ h,  const float* __restrict__ Ww,
    const float* __restrict__ Wb, const float* __restrict__ aiw,
    const float* __restrict__ aib, const float* __restrict__ ajw,
    const float* __restrict__ ajb)
{
    __shared__ float hS[TK][TM + 4];
    __shared__ float wS[TK][F_];

    const int t    = threadIdx.x;
    const int row0 = blockIdx.x * TM;
    const int tf   = t & 31;
    const int ti   = t >> 5;
    const int lr   = t >> 2;
    const int lc   = (t & 3) * 8;

    float c[8][8];
#pragma unroll
    for (int i = 0; i < 8; i++)
#pragma unroll
        for (int j = 0; j < 8; j++) c[i][j] = 0.f;

    for (int k0 = 0; k0 < F_; k0 += TK) {
        float4 v0 = *(const float4*)&h[(row0 + lr) * F_ + k0 + lc];
        float4 v1 = *(const float4*)&h[(row0 + lr) * F_ + k0 + lc + 4];
        hS[lc + 0][lr] = v0.x; hS[lc + 1][lr] = v0.y;
        hS[lc + 2][lr] = v0.z; hS[lc + 3][lr] = v0.w;
        hS[lc + 4][lr] = v1.x; hS[lc + 5][lr] = v1.y;
        hS[lc + 6][lr] = v1.z; hS[lc + 7][lr] = v1.w;

#pragma unroll
        for (int q = 0; q < 4; q++) {
            int o = (t >> 2) + q * 64;
            const float* wp = &Ww[o * F_ + k0 + (t & 3) * 8];
            float4 w4 = *(const float4*)wp;
            float4 w5 = *(const float4*)(wp + 4);
            int kk = (t & 3) * 8;
            wS[kk + 0][o] = w4.x; wS[kk + 1][o] = w4.y;
            wS[kk + 2][o] = w4.z; wS[kk + 3][o] = w4.w;
            wS[kk + 4][o] = w5.x; wS[kk + 5][o] = w5.y;
            wS[kk + 6][o] = w5.z; wS[kk + 7][o] = w5.w;
        }
        __syncthreads();

#pragma unroll 4
        for (int kk = 0; kk < TK; kk++) {
            float a[8], bb[8];
            *(float4*)(a)      = *(const float4*)&hS[kk][ti * 8];
            *(float4*)(a + 4)  = *(const float4*)&hS[kk][ti * 8 + 4];
            *(float4*)(bb)     = *(const float4*)&wS[kk][tf * 8];
            *(float4*)(bb + 4) = *(const float4*)&wS[kk][tf * 8 + 4];
#pragma unroll
            for (int i = 0; i < 8; i++)
#pragma unroll
                for (int j = 0; j < 8; j++)
                    c[i][j] = fmaf(a[i], bb[j], c[i][j]);
        }
        __syncthreads();
    }

    float bv[8], av[8], jv[8];
#pragma unroll
    for (int u = 0; u < 8; u++) {
        bv[u] = Wb[tf * 8 + u];
        av[u] = aiw[tf * 8 + u];
        jv[u] = ajw[tf * 8 + u];
    }
    const float aib0 = aib[0], ajb0 = ajb[0];

#pragma unroll
    for (int ii = 0; ii < 8; ii++) {
        int row = row0 + ti * 8 + ii;
        float p1 = 0.f, p2 = 0.f;
#pragma unroll
        for (int u = 0; u < 8; u++) {
            c[ii][u] += bv[u];
            p1 = fmaf(c[ii][u], av[u], p1);
            p2 = fmaf(c[ii][u], jv[u], p2);
        }
#pragma unroll
        for (int off = 16; off > 0; off >>= 1) {
            p1 += __shfl_xor_sync(0xffffffffu, p1, off);
            p2 += __shfl_xor_sync(0xffffffffu, p2, off);
        }
        if (tf == 0) {
            g_s1[row] = p1 + aib0;
            g_s2[row] = p2 + ajb0;
        }
    }

    const int b  = row0 >> 11;
    const int jb = (row0 & (N_ - 1)) + ti * 8;
#pragma unroll
    for (int u = 0; u < 8; u++) {
        int f = tf * 8 + u;
        uint32_t hw[4], lw[4];
#pragma unroll
        for (int e = 0; e < 8; e += 2) {
            float v0 = c[e][u], v1 = c[e + 1][u];
            __half h0 = __float2half_rn(v0), h1 = __float2half_rn(v1);
            float r0 = v0 - __half2float(h0);
            float r1 = v1 - __half2float(h1);
            __half l0 = __float2half_rn(r0), l1 = __float2half_rn(r1);
            __half2 hp = __halves2half2(h0, h1);
            __half2 lp = __halves2half2(l0, l1);
            hw[e >> 1] = *(uint32_t*)&hp;
            lw[e >> 1] = *(uint32_t*)&lp;
        }
        size_t dst = ((size_t)(b * F_ + f)) * N_ + jb;
        *(uint4*)(g_WhT_hi + dst) = make_uint4(hw[0], hw[1], hw[2], hw[3]);
        *(uint4*)(g_WhT_lo + dst) = make_uint4(lw[0], lw[1], lw[2], lw[3]);
    }
}

// ---------------------------------------------------------------------------
// Kernel 2: HMMA attention GEMM, fp16 2-term split (A single, B hi/lo).
//   CTA 128i x 256f, 512 thr, 1 sync/chunk; next chunk's exp compute
//   interleaved into the MMA block; B via cp.async at segment start.
// ---------------------------------------------------------------------------
#define KC2   32
#define NCH2  (N_ / KC2)                  // 64 chunks
#define AST   40
#define BST   40
#define A_BYTES (128 * AST * 2)           // 10240 (A hi only)
#define B_BYTES (256 * BST * 2)           // 20480
#define STAGE   (A_BYTES + 2 * B_BYTES)   // 51200
#define DYN_SMEM (2 * STAGE)              // 102400

__global__ void __launch_bounds__(512, 1) k2_attn(
    const int* __restrict__ adj, float* __restrict__ out)
{
    extern __shared__ __align__(16) char smRaw[];
    __shared__ float s1S[128];
    __shared__ __align__(16) float s2S[N_];   // 8KB: whole batch s2 row
    __shared__ float rsS[128][4];
    __shared__ float rInv[128];

    const int t    = threadIdx.x;
    const int lane = t & 31;
    const int wid  = t >> 5;
    const int wm   = wid & 3;
    const int wn   = wid >> 2;
    const int b    = blockIdx.x >> 4;
    const int i0   = (blockIdx.x & 15) * 128;

    const uint32_t smBase = smem_u32(smRaw);

    if (t < 128) s1S[t] = g_s1[b * N_ + i0 + t];
    {
        const float4* s2g = (const float4*)(g_s2 + b * N_);
#pragma unroll
        for (int k = t; k < N_ / 4; k += 512) ((float4*)s2S)[k] = s2g[k];
    }

    // ---- roles ----
    const int ig = t >> 2;                   // A row 0..127
    const int jg = (t & 3) * 8;              // 8-j subgroup
    const int fB = t >> 1;                   // B row 0..255
    const int hB = (t & 1) * 16;

    const int* adjP = adj + (size_t)(b * N_ + i0 + ig) * N_;
    const __half* bhP = g_WhT_hi + (size_t)(b * F_ + fB) * N_;
    const __half* blP = g_WhT_lo + (size_t)(b * F_ + fB) * N_;

    float acc[2][8][4];
#pragma unroll
    for (int m = 0; m < 2; m++)
#pragma unroll
        for (int n = 0; n < 8; n++)
#pragma unroll
            for (int q = 0; q < 4; q++) acc[m][n][q] = 0.f;
    float lsum = 0.f;

    uint32_t hw[4];             // w half2-pairs for the upcoming chunk

    __syncthreads();            // s1S/s2S visible

    // ---- prologue: wreg(0), B(0), A(0) ----
    {
        int4 a0 = *(const int4*)(adjP + jg);
        int4 a1 = *(const int4*)(adjP + jg + 4);
        const float s1v = s1S[ig];
        make_w_pair(s1v, a0.x, a0.y, s2S[jg + 0], s2S[jg + 1], lsum, hw[0]);
        make_w_pair(s1v, a0.z, a0.w, s2S[jg + 2], s2S[jg + 3], lsum, hw[1]);
        make_w_pair(s1v, a1.x, a1.y, s2S[jg + 4], s2S[jg + 5], lsum, hw[2]);
        make_w_pair(s1v, a1.z, a1.w, s2S[jg + 6], s2S[jg + 7], lsum, hw[3]);

        uint32_t dH = smBase + A_BYTES + (uint32_t)(fB * BST + hB) * 2u;
        cp_async16(dH,      bhP + hB);
        cp_async16(dH + 16, bhP + hB + 8);
        cp_async16(dH + B_BYTES,      blP + hB);
        cp_async16(dH + B_BYTES + 16, blP + hB + 8);
        CP_COMMIT();

        uint32_t off = (uint32_t)(ig * AST + jg) * 2u;
        asm volatile("st.shared.v4.b32 [%0], {%1,%2,%3,%4};"
                     :: "r"(smBase + off), "r"(hw[0]), "r"(hw[1]), "r"(hw[2]), "r"(hw[3]));
        CP_WAIT0();
    }
    __syncthreads();

    for (int c = 0; c < NCH2; ++c) {
        const uint32_t sb   = smBase + (c & 1) * STAGE;
        const uint32_t sbN  = smBase + ((c + 1) & 1) * STAGE;
        const uint32_t aS   = sb;
        const uint32_t bHiS = sb + A_BYTES;
        const uint32_t bLoS = bHiS + B_BYTES;
        const bool doNext = (c + 1 < NCH2);
        const int  jn = (c + 1) * KC2;

        // ---- segment start: launch B(c+1) + adj(c+1) loads (fly under MMAs) ----
        int4 pA0, pA1;
        if (doNext) {
            uint32_t dH = sbN + A_BYTES + (uint32_t)(fB * BST + hB) * 2u;
            cp_async16(dH,      bhP + jn + hB);
            cp_async16(dH + 16, bhP + jn + hB + 8);
            cp_async16(dH + B_BYTES,      blP + jn + hB);
            cp_async16(dH + B_BYTES + 16, blP + jn + hB + 8);
            CP_COMMIT();
            pA0 = *(const int4*)(adjP + jn + jg);
            pA1 = *(const int4*)(adjP + jn + jg + 4);
        }
        const float s1v = s1S[ig];

        // ---- MMA(c), with wreg(c+1) computes interleaved in the same block ----
#pragma unroll
        for (int ks = 0; ks < 2; ++ks) {
            const int k0 = ks * 16;
            uint32_t ah[2][4];
#pragma unroll
            for (int mt = 0; mt < 2; ++mt) {
                int arow = wm * 32 + mt * 16 + (lane & 15);
                uint32_t aoff = (uint32_t)(arow * AST + k0 + ((lane >> 4) << 3)) * 2u;
                ldm_x4(ah[mt][0], ah[mt][1], ah[mt][2], ah[mt][3], aS + aoff);
            }
#pragma unroll
            for (int pr = 0; pr < 4; ++pr) {
                int n0   = wn * 64 + pr * 16;
                int rowB = n0 + (lane & 7) + ((lane >> 4) << 3);
                int colB = k0 + (((lane >> 3) & 1) << 3);
                uint32_t boff = (uint32_t)(rowB * BST + colB) * 2u;
                uint32_t bh0, bh1, bh2, bh3, bl0, bl1, bl2, bl3;
                ldm_x4(bh0, bh1, bh2, bh3, bHiS + boff);
                ldm_x4(bl0, bl1, bl2, bl3, bLoS + boff);
                // term a*b_hi (4 independent accumulators)
                mma_f16(acc[0][pr * 2],     ah[0], bh0, bh1);
                mma_f16(acc[1][pr * 2],     ah[1], bh0, bh1);
                mma_f16(acc[0][pr * 2 + 1], ah[0], bh2, bh3);
                mma_f16(acc[1][pr * 2 + 1], ah[1], bh2, bh3);
                // term a*b_lo
                mma_f16(acc[0][pr * 2],     ah[0], bl0, bl1);
                mma_f16(acc[1][pr * 2],     ah[1], bl0, bl1);
                mma_f16(acc[0][pr * 2 + 1], ah[0], bl2, bl3);
                mma_f16(acc[1][pr * 2 + 1], ah[1], bl2, bl3);

                // interleaved next-chunk w computes (independent of MMAs)
                if (doNext && ks == 1) {
                    int a0 = (pr < 2) ? ((pr == 0) ? pA0.x : pA0.z)
                                      : ((pr == 2) ? pA1.x : pA1.z);
                    int a1 = (pr < 2) ? ((pr == 0) ? pA0.y : pA0.w)
                                      : ((pr == 2) ? pA1.y : pA1.w);
                    make_w_pair(s1v, a0, a1,
                                s2S[jn + jg + 2 * pr], s2S[jn + jg + 2 * pr + 1],
                                lsum, hw[pr]);
                }
            }
        }

        // ---- segment end: store A(c+1), drain B(c+1) ----
        if (doNext) {
            uint32_t off = (uint32_t)(ig * AST + jg) * 2u;
            asm volatile("st.shared.v4.b32 [%0], {%1,%2,%3,%4};"
                         :: "r"(sbN + off), "r"(hw[0]), "r"(hw[1]), "r"(hw[2]), "r"(hw[3]));
            CP_WAIT0();
        }
        __syncthreads();
    }

    // ---- row-sum reduce ----
    rsS[ig][t & 3] = lsum;
    __syncthreads();
    if (t < 128) rInv[t] = 1.f / (rsS[t][0] + rsS[t][1] + rsS[t][2] + rsS[t][3]);
    __syncthreads();

    // ---- epilogue: normalize + ELU + store ----
    const int g  = lane >> 2;
    const int tq = lane & 3;
#pragma unroll
    for (int mt = 0; mt < 2; ++mt) {
        int r0l = wm * 32 + mt * 16 + g;
        int r1l = r0l + 8;
        float inv0 = rInv[r0l], inv1 = rInv[r1l];
        size_t o0 = ((size_t)(b * N_ + i0 + r0l)) * F_;
        size_t o1 = ((size_t)(b * N_ + i0 + r1l)) * F_;
#pragma unroll
        for (int nt = 0; nt < 8; ++nt) {
            int col = wn * 64 + nt * 8 + 2 * tq;
            float x0 = acc[mt][nt][0] * inv0;
            float x1 = acc[mt][nt][1] * inv0;
            float x2 = acc[mt][nt][2] * inv1;
            float x3 = acc[mt][nt][3] * inv1;
            x0 = (x0 > 0.f) ? x0 : expm1f(x0);
            x1 = (x1 > 0.f) ? x1 : expm1f(x1);
            x2 = (x2 > 0.f) ? x2 : expm1f(x2);
            x3 = (x3 > 0.f) ? x3 : expm1f(x3);
            *(float2*)(out + o0 + col) = make_float2(x0, x1);
            *(float2*)(out + o1 + col) = make_float2(x2, x3);
        }
    }
}

// ---------------------------------------------------------------------------
extern "C" void kernel_launch(void* const* d_in, const int* in_sizes, int n_in,
                              void* d_out, int out_size)
{
    const float* h   = (const float*)d_in[0];
    const int*   adj = (const int*)  d_in[1];
    const float* Ww  = (const float*)d_in[2];
    const float* Wb  = (const float*)d_in[3];
    const float* aiw = (const float*)d_in[4];
    const float* aib = (const float*)d_in[5];
    const float* ajw = (const float*)d_in[6];
    const float* ajb = (const float*)d_in[7];
    float* out = (float*)d_out;

    static bool attrDone = false;
    if (!attrDone) {
        cudaFuncSetAttribute(k2_attn, cudaFuncAttributeMaxDynamicSharedMemorySize,
                             DYN_SMEM);
        attrDone = true;
    }

    k1_gemm<<<(B_ * N_) / TM, 256>>>(h, Ww, Wb, aiw, aib, ajw, ajb);
    k2_attn<<<B_ * (N_ / 128), 512, DYN_SMEM>>>(adj, out);
}

// round 9
// speedup vs baseline: 1.0110x; 1.0110x over previous
#include <cuda_runtime.h>
#include <cuda_bf16.h>
#include <math.h>
#include <cstdint>
#include <cstddef>

#define B_   8
#define N_   2048
#define F_   256
#define TM   64
#define TK   32
#define ALPHA 0.2f

// ---------------- device scratch (allocation-free rule) ----------------
__device__ float g_s1[B_ * N_];
__device__ float g_s2[B_ * N_];
__device__ __nv_bfloat16 g_WhT_hi[B_ * F_ * N_];   // [b][f][j]
__device__ __nv_bfloat16 g_WhT_lo[B_ * F_ * N_];

__device__ __forceinline__ uint32_t smem_u32(const void* p) {
    uint32_t a;
    asm("{ .reg .u64 t; cvta.to.shared.u64 t, %1; cvt.u32.u64 %0, t; }"
        : "=r"(a) : "l"(p));
    return a;
}
__device__ __forceinline__ void ldm_x4(uint32_t& r0, uint32_t& r1,
                                       uint32_t& r2, uint32_t& r3, uint32_t addr) {
    asm volatile("ldmatrix.sync.aligned.m8n8.x4.shared.b16 {%0,%1,%2,%3}, [%4];"
                 : "=r"(r0), "=r"(r1), "=r"(r2), "=r"(r3) : "r"(addr));
}
__device__ __forceinline__ void mma_bf16(float* d, const uint32_t* a,
                                         uint32_t b0, uint32_t b1) {
    asm volatile(
        "mma.sync.aligned.m16n8k16.row.col.f32.bf16.bf16.f32 "
        "{%0,%1,%2,%3}, {%4,%5,%6,%7}, {%8,%9}, {%0,%1,%2,%3};"
        : "+f"(d[0]), "+f"(d[1]), "+f"(d[2]), "+f"(d[3])
        : "r"(a[0]), "r"(a[1]), "r"(a[2]), "r"(a[3]), "r"(b0), "r"(b1));
}
__device__ __forceinline__ void cp_async16(uint32_t dst, const void* src) {
    asm volatile("cp.async.cg.shared.global [%0], [%1], 16;"
                 :: "r"(dst), "l"(src) : "memory");
}
#define CP_COMMIT() asm volatile("cp.async.commit_group;" ::: "memory")
#define CP_WAIT0()  asm volatile("cp.async.wait_group 0;" ::: "memory")

// w-pair: leaky+exp+mask, bf16 hi/lo split, rowsum accumulate
__device__ __forceinline__ void make_w_pair(float s1v, int a0, int a1,
                                            float s20, float s21,
                                            float& lsum, uint32_t& hiP, uint32_t& loP)
{
    float x0 = s1v + s20; x0 = fmaxf(x0, ALPHA * x0);
    float x1 = s1v + s21; x1 = fmaxf(x1, ALPHA * x1);
    float w0 = (a0 > 0) ? __expf(x0) : 0.f;
    float w1 = (a1 > 0) ? __expf(x1) : 0.f;
    lsum += w0 + w1;
    __nv_bfloat16 h0 = __float2bfloat16(w0), h1 = __float2bfloat16(w1);
    float r0 = w0 - __bfloat162float(h0);
    float r1 = w1 - __bfloat162float(h1);
    __nv_bfloat16 l0 = __float2bfloat16(r0), l1 = __float2bfloat16(r1);
    __nv_bfloat162 hp = __halves2bfloat162(h0, h1);
    __nv_bfloat162 lp = __halves2bfloat162(l0, l1);
    hiP = *(uint32_t*)&hp;
    loP = *(uint32_t*)&lp;
}

// ---------------------------------------------------------------------------
// Kernel 1: Wh = h @ W^T + b ; emits WhT hi/lo (bf16 split, [b][f][j]) + s1/s2
// ---------------------------------------------------------------------------
__global__ void __launch_bounds__(256) k1_gemm(
    const float* __restrict__ h,  const float* __restrict__ Ww,
    const float* __restrict__ Wb, const float* __restrict__ aiw,
    const float* __restrict__ aib, const float* __restrict__ ajw,
    const float* __restrict__ ajb)
{
    __shared__ float hS[TK][TM + 4];
    __shared__ float wS[TK][F_];

    const int t    = threadIdx.x;
    const int row0 = blockIdx.x * TM;
    const int tf   = t & 31;
    const int ti   = t >> 5;
    const int lr   = t >> 2;
    const int lc   = (t & 3) * 8;

    float c[8][8];
#pragma unroll
    for (int i = 0; i < 8; i++)
#pragma unroll
        for (int j = 0; j < 8; j++) c[i][j] = 0.f;

    for (int k0 = 0; k0 < F_; k0 += TK) {
        float4 v0 = *(const float4*)&h[(row0 + lr) * F_ + k0 + lc];
        float4 v1 = *(const float4*)&h[(row0 + lr) * F_ + k0 + lc + 4];
        hS[lc + 0][lr] = v0.x; hS[lc + 1][lr] = v0.y;
        hS[lc + 2][lr] = v0.z; hS[lc + 3][lr] = v0.w;
        hS[lc + 4][lr] = v1.x; hS[lc + 5][lr] = v1.y;
        hS[lc + 6][lr] = v1.z; hS[lc + 7][lr] = v1.w;

#pragma unroll
        for (int q = 0; q < 4; q++) {
            int o = (t >> 2) + q * 64;
            const float* wp = &Ww[o * F_ + k0 + (t & 3) * 8];
            float4 w4 = *(const float4*)wp;
            float4 w5 = *(const float4*)(wp + 4);
            int kk = (t & 3) * 8;
            wS[kk + 0][o] = w4.x; wS[kk + 1][o] = w4.y;
            wS[kk + 2][o] = w4.z; wS[kk + 3][o] = w4.w;
            wS[kk + 4][o] = w5.x; wS[kk + 5][o] = w5.y;
            wS[kk + 6][o] = w5.z; wS[kk + 7][o] = w5.w;
        }
        __syncthreads();

#pragma unroll 4
        for (int kk = 0; kk < TK; kk++) {
            float a[8], bb[8];
            *(float4*)(a)      = *(const float4*)&hS[kk][ti * 8];
            *(float4*)(a + 4)  = *(const float4*)&hS[kk][ti * 8 + 4];
            *(float4*)(bb)     = *(const float4*)&wS[kk][tf * 8];
            *(float4*)(bb + 4) = *(const float4*)&wS[kk][tf * 8 + 4];
#pragma unroll
            for (int i = 0; i < 8; i++)
#pragma unroll
                for (int j = 0; j < 8; j++)
                    c[i][j] = fmaf(a[i], bb[j], c[i][j]);
        }
        __syncthreads();
    }

    float bv[8], av[8], jv[8];
#pragma unroll
    for (int u = 0; u < 8; u++) {
        bv[u] = Wb[tf * 8 + u];
        av[u] = aiw[tf * 8 + u];
        jv[u] = ajw[tf * 8 + u];
    }
    const float aib0 = aib[0], ajb0 = ajb[0];

#pragma unroll
    for (int ii = 0; ii < 8; ii++) {
        int row = row0 + ti * 8 + ii;
        float p1 = 0.f, p2 = 0.f;
#pragma unroll
        for (int u = 0; u < 8; u++) {
            c[ii][u] += bv[u];
            p1 = fmaf(c[ii][u], av[u], p1);
            p2 = fmaf(c[ii][u], jv[u], p2);
        }
#pragma unroll
        for (int off = 16; off > 0; off >>= 1) {
            p1 += __shfl_xor_sync(0xffffffffu, p1, off);
            p2 += __shfl_xor_sync(0xffffffffu, p2, off);
        }
        if (tf == 0) {
            g_s1[row] = p1 + aib0;
            g_s2[row] = p2 + ajb0;
        }
    }

    const int b  = row0 >> 11;
    const int jb = (row0 & (N_ - 1)) + ti * 8;
#pragma unroll
    for (int u = 0; u < 8; u++) {
        int f = tf * 8 + u;
        uint32_t hw[4], lw[4];
#pragma unroll
        for (int e = 0; e < 8; e += 2) {
            float v0 = c[e][u], v1 = c[e + 1][u];
            __nv_bfloat16 h0 = __float2bfloat16(v0), h1 = __float2bfloat16(v1);
            float r0 = v0 - __bfloat162float(h0);
            float r1 = v1 - __bfloat162float(h1);
            __nv_bfloat16 l0 = __float2bfloat16(r0), l1 = __float2bfloat16(r1);
            __nv_bfloat162 hp = __halves2bfloat162(h0, h1);
            __nv_bfloat162 lp = __halves2bfloat162(l0, l1);
            hw[e >> 1] = *(uint32_t*)&hp;
            lw[e >> 1] = *(uint32_t*)&lp;
        }
        size_t dst = ((size_t)(b * F_ + f)) * N_ + jb;
        *(uint4*)(g_WhT_hi + dst) = make_uint4(hw[0], hw[1], hw[2], hw[3]);
        *(uint4*)(g_WhT_lo + dst) = make_uint4(lw[0], lw[1], lw[2], lw[3]);
    }
}

// ---------------------------------------------------------------------------
// Kernel 2: HMMA attention GEMM, bf16 3-term split.
//   CTA 64i x 256f, 256 thr, 2 CTAs/SM (co-resident phase overlap).
//   Grid 256 CTAs (all 148 SMs busy). 1 sync/chunk; next chunk's exp
//   interleaved into the MMA block; B via cp.async at segment start.
// ---------------------------------------------------------------------------
#define KC2   32
#define NCH2  (N_ / KC2)                  // 64 chunks
#define TILE_M2 64
#define AST   40
#define BST   40
#define A_BYTES (TILE_M2 * AST * 2)       // 5120
#define B_BYTES (256 * BST * 2)           // 20480
#define STAGE   (2 * A_BYTES + 2 * B_BYTES)   // 51200
#define DYN_SMEM (2 * STAGE)                  // 102400

__global__ void __launch_bounds__(256, 2) k2_attn(
    const int* __restrict__ adj, float* __restrict__ out)
{
    extern __shared__ __align__(16) char smRaw[];
    __shared__ float s1S[TILE_M2];
    __shared__ __align__(16) float s2S[N_];   // 8KB: whole batch s2 row
    __shared__ float rsS[TILE_M2][4];
    __shared__ float rInv[TILE_M2];

    const int t    = threadIdx.x;
    const int lane = t & 31;
    const int wid  = t >> 5;             // 0..7
    const int wm   = wid & 1;            // i: wm*32
    const int wn   = wid >> 1;           // f: wn*64 (0..3)
    const int b    = blockIdx.x >> 5;    // 32 i-tiles per batch
    const int i0   = (blockIdx.x & 31) * TILE_M2;

    const uint32_t smBase = smem_u32(smRaw);

    if (t < TILE_M2) s1S[t] = g_s1[b * N_ + i0 + t];
    {
        const float4* s2g = (const float4*)(g_s2 + b * N_);
#pragma unroll
        for (int k = t; k < N_ / 4; k += 256) ((float4*)s2S)[k] = s2g[k];
    }

    // ---- roles ----
    const int ig = t >> 2;                   // A row 0..63
    const int jg = (t & 3) * 8;              // 8-j subgroup
    const int fB = t;                        // B row 0..255 (one full row each)

    const int* adjP = adj + (size_t)(b * N_ + i0 + ig) * N_;
    const __nv_bfloat16* bhP = g_WhT_hi + (size_t)(b * F_ + fB) * N_;
    const __nv_bfloat16* blP = g_WhT_lo + (size_t)(b * F_ + fB) * N_;

    float acc[2][8][4];
#pragma unroll
    for (int m = 0; m < 2; m++)
#pragma unroll
        for (int n = 0; n < 8; n++)
#pragma unroll
            for (int q = 0; q < 4; q++) acc[m][n][q] = 0.f;
    float lsum = 0.f;

    uint32_t hw[4], lw[4];      // w-pairs for the upcoming chunk

    __syncthreads();            // s1S/s2S visible

    // ---- prologue: wreg(0), B(0), A(0) ----
    {
        int4 a0 = *(const int4*)(adjP + jg);
        int4 a1 = *(const int4*)(adjP + jg + 4);
        const float s1v = s1S[ig];
        make_w_pair(s1v, a0.x, a0.y, s2S[jg + 0], s2S[jg + 1], lsum, hw[0], lw[0]);
        make_w_pair(s1v, a0.z, a0.w, s2S[jg + 2], s2S[jg + 3], lsum, hw[1], lw[1]);
        make_w_pair(s1v, a1.x, a1.y, s2S[jg + 4], s2S[jg + 5], lsum, hw[2], lw[2]);
        make_w_pair(s1v, a1.z, a1.w, s2S[jg + 6], s2S[jg + 7], lsum, hw[3], lw[3]);

        uint32_t dH = smBase + 2 * A_BYTES + (uint32_t)(fB * BST) * 2u;
        cp_async16(dH,      bhP);
        cp_async16(dH + 16, bhP + 8);
        cp_async16(dH + 32, bhP + 16);
        cp_async16(dH + 48, bhP + 24);
        uint32_t dL = dH + B_BYTES;
        cp_async16(dL,      blP);
        cp_async16(dL + 16, blP + 8);
        cp_async16(dL + 32, blP + 16);
        cp_async16(dL + 48, blP + 24);
        CP_COMMIT();

        uint32_t off = (uint32_t)(ig * AST + jg) * 2u;
        asm volatile("st.shared.v4.b32 [%0], {%1,%2,%3,%4};"
                     :: "r"(smBase + off), "r"(hw[0]), "r"(hw[1]), "r"(hw[2]), "r"(hw[3]));
        asm volatile("st.shared.v4.b32 [%0], {%1,%2,%3,%4};"
                     :: "r"(smBase + A_BYTES + off), "r"(lw[0]), "r"(lw[1]), "r"(lw[2]), "r"(lw[3]));
        CP_WAIT0();
    }
    __syncthreads();

    for (int c = 0; c < NCH2; ++c) {
        const uint32_t sb   = smBase + (c & 1) * STAGE;
        const uint32_t sbN  = smBase + ((c + 1) & 1) * STAGE;
        const uint32_t aHiS = sb;
        const uint32_t aLoS = sb + A_BYTES;
        const uint32_t bHiS = sb + 2 * A_BYTES;
        const uint32_t bLoS = bHiS + B_BYTES;
        const bool doNext = (c + 1 < NCH2);
        const int  jn = (c + 1) * KC2;

        // ---- segment start: launch B(c+1) + adj(c+1) loads (fly under MMAs) ----
        int4 pA0, pA1;
        if (doNext) {
            uint32_t dH = sbN + 2 * A_BYTES + (uint32_t)(fB * BST) * 2u;
            cp_async16(dH,      bhP + jn);
            cp_async16(dH + 16, bhP + jn + 8);
            cp_async16(dH + 32, bhP + jn + 16);
            cp_async16(dH + 48, bhP + jn + 24);
            uint32_t dL = dH + B_BYTES;
            cp_async16(dL,      blP + jn);
            cp_async16(dL + 16, blP + jn + 8);
            cp_async16(dL + 32, blP + jn + 16);
            cp_async16(dL + 48, blP + jn + 24);
            CP_COMMIT();
            pA0 = *(const int4*)(adjP + jn + jg);
            pA1 = *(const int4*)(adjP + jn + jg + 4);
        }
        const float s1v = s1S[ig];

        // ---- MMA(c), with wreg(c+1) computes interleaved in the same block ----
#pragma unroll
        for (int ks = 0; ks < 2; ++ks) {
            const int k0 = ks * 16;
            uint32_t ah[2][4], al[2][4];
#pragma unroll
            for (int mt = 0; mt < 2; ++mt) {
                int arow = wm * 32 + mt * 16 + (lane & 15);
                uint32_t aoff = (uint32_t)(arow * AST + k0 + ((lane >> 4) << 3)) * 2u;
                ldm_x4(ah[mt][0], ah[mt][1], ah[mt][2], ah[mt][3], aHiS + aoff);
                ldm_x4(al[mt][0], al[mt][1], al[mt][2], al[mt][3], aLoS + aoff);
            }
#pragma unroll
            for (int pr = 0; pr < 4; ++pr) {
                int n0   = wn * 64 + pr * 16;
                int rowB = n0 + (lane & 7) + ((lane >> 4) << 3);
                int colB = k0 + (((lane >> 3) & 1) << 3);
                uint32_t boff = (uint32_t)(rowB * BST + colB) * 2u;
                uint32_t bh0, bh1, bh2, bh3, bl0, bl1, bl2, bl3;
                ldm_x4(bh0, bh1, bh2, bh3, bHiS + boff);
                ldm_x4(bl0, bl1, bl2, bl3, bLoS + boff);
                mma_bf16(acc[0][pr * 2],     ah[0], bh0, bh1);
                mma_bf16(acc[1][pr * 2],     ah[1], bh0, bh1);
                mma_bf16(acc[0][pr * 2 + 1], ah[0], bh2, bh3);
                mma_bf16(acc[1][pr * 2 + 1], ah[1], bh2, bh3);
                mma_bf16(acc[0][pr * 2],     ah[0], bl0, bl1);
                mma_bf16(acc[1][pr * 2],     ah[1], bl0, bl1);
                mma_bf16(acc[0][pr * 2 + 1], ah[0], bl2, bl3);
                mma_bf16(acc[1][pr * 2 + 1], ah[1], bl2, bl3);
                mma_bf16(acc[0][pr * 2],     al[0], bh0, bh1);
                mma_bf16(acc[1][pr * 2],     al[1], bh0, bh1);
                mma_bf16(acc[0][pr * 2 + 1], al[0], bh2, bh3);
                mma_bf16(acc[1][pr * 2 + 1], al[1], bh2, bh3);

                // interleaved next-chunk w computes (independent of MMAs)
                if (doNext && ks == 1) {
                    int a0 = (pr < 2) ? ((pr == 0) ? pA0.x : pA0.z)
                                      : ((pr == 2) ? pA1.x : pA1.z);
                    int a1 = (pr < 2) ? ((pr == 0) ? pA0.y : pA0.w)
                                      : ((pr == 2) ? pA1.y : pA1.w);
                    make_w_pair(s1v, a0, a1,
                                s2S[jn + jg + 2 * pr], s2S[jn + jg + 2 * pr + 1],
                                lsum, hw[pr], lw[pr]);
                }
            }
        }

        // ---- segment end: store A(c+1), drain B(c+1) ----
        if (doNext) {
            uint32_t off = (uint32_t)(ig * AST + jg) * 2u;
            asm volatile("st.shared.v4.b32 [%0], {%1,%2,%3,%4};"
                         :: "r"(sbN + off), "r"(hw[0]), "r"(hw[1]), "r"(hw[2]), "r"(hw[3]));
            asm volatile("st.shared.v4.b32 [%0], {%1,%2,%3,%4};"
                         :: "r"(sbN + A_BYTES + off), "r"(lw[0]), "r"(lw[1]), "r"(lw[2]), "r"(lw[3]));
            CP_WAIT0();
        }
        __syncthreads();
    }

    // ---- row-sum reduce ----
    rsS[ig][t & 3] = lsum;
    __syncthreads();
    if (t < TILE_M2) rInv[t] = 1.f / (rsS[t][0] + rsS[t][1] + rsS[t][2] + rsS[t][3]);
    __syncthreads();

    // ---- epilogue: normalize + ELU + store ----
    const int g  = lane >> 2;
    const int tq = lane & 3;
#pragma unroll
    for (int mt = 0; mt < 2; ++mt) {
        int r0l = wm * 32 + mt * 16 + g;
        int r1l = r0l + 8;
        float inv0 = rInv[r0l], inv1 = rInv[r1l];
        size_t o0 = ((size_t)(b * N_ + i0 + r0l)) * F_;
        size_t o1 = ((size_t)(b * N_ + i0 + r1l)) * F_;
#pragma unroll
        for (int nt = 0; nt < 8; ++nt) {
            int col = wn * 64 + nt * 8 + 2 * tq;
            float x0 = acc[mt][nt][0] * inv0;
            float x1 = acc[mt][nt][1] * inv0;
            float x2 = acc[mt][nt][2] * inv1;
            float x3 = acc[mt][nt][3] * inv1;
            x0 = (x0 > 0.f) ? x0 : expm1f(x0);
            x1 = (x1 > 0.f) ? x1 : expm1f(x1);
            x2 = (x2 > 0.f) ? x2 : expm1f(x2);
            x3 = (x3 > 0.f) ? x3 : expm1f(x3);
            *(float2*)(out + o0 + col) = make_float2(x0, x1);
            *(float2*)(out + o1 + col) = make_float2(x2, x3);
        }
    }
}

// ---------------------------------------------------------------------------
extern "C" void kernel_launch(void* const* d_in, const int* in_sizes, int n_in,
                              void* d_out, int out_size)
{
    const float* h   = (const float*)d_in[0];
    const int*   adj = (const int*)  d_in[1];
    const float* Ww  = (const float*)d_in[2];
    const float* Wb  = (const float*)d_in[3];
    const float* aiw = (const float*)d_in[4];
    const float* aib = (const float*)d_in[5];
    const float* ajw = (const float*)d_in[6];
    const float* ajb = (const float*)d_in[7];
    float* out = (float*)d_out;

    static bool attrDone = false;
    if (!attrDone) {
        cudaFuncSetAttribute(k2_attn, cudaFuncAttributeMaxDynamicSharedMemorySize,
                             DYN_SMEM);
        attrDone = true;
    }

    k1_gemm<<<(B_ * N_) / TM, 256>>>(h, Ww, Wb, aiw, aib, ajw, ajb);
    k2_attn<<<B_ * (N_ / TILE_M2), 256, DYN_SMEM>>>(adj, out);
}

// round 10
// speedup vs baseline: 1.5873x; 1.5701x over previous
#include <cuda_runtime.h>
#include <cuda_bf16.h>
#include <math.h>
#include <cstdint>
#include <cstddef>

#define B_   8
#define N_   2048
#define F_   256
#define ALPHA 0.2f

// ---------------- device scratch (allocation-free rule) ----------------
__device__ float g_s1[B_ * N_];
__device__ float g_s2[B_ * N_];
__device__ float g_Wh[B_ * N_ * F_];               // fp32 Wh (k1 -> k1t)
__device__ __nv_bfloat16 g_WhT_hi[B_ * F_ * N_];   // [b][f][j]
__device__ __nv_bfloat16 g_WhT_lo[B_ * F_ * N_];
__device__ __nv_bfloat16 gW_hi[F_ * F_];           // W split, [out][k]
__device__ __nv_bfloat16 gW_lo[F_ * F_];

__device__ __forceinline__ uint32_t smem_u32(const void* p) {
    uint32_t a;
    asm("{ .reg .u64 t; cvta.to.shared.u64 t, %1; cvt.u32.u64 %0, t; }"
        : "=r"(a) : "l"(p));
    return a;
}
__device__ __forceinline__ void ldm_x4(uint32_t& r0, uint32_t& r1,
                                       uint32_t& r2, uint32_t& r3, uint32_t addr) {
    asm volatile("ldmatrix.sync.aligned.m8n8.x4.shared.b16 {%0,%1,%2,%3}, [%4];"
                 : "=r"(r0), "=r"(r1), "=r"(r2), "=r"(r3) : "r"(addr));
}
__device__ __forceinline__ void mma_bf16(float* d, const uint32_t* a,
                                         uint32_t b0, uint32_t b1) {
    asm volatile(
        "mma.sync.aligned.m16n8k16.row.col.f32.bf16.bf16.f32 "
        "{%0,%1,%2,%3}, {%4,%5,%6,%7}, {%8,%9}, {%0,%1,%2,%3};"
        : "+f"(d[0]), "+f"(d[1]), "+f"(d[2]), "+f"(d[3])
        : "r"(a[0]), "r"(a[1]), "r"(a[2]), "r"(a[3]), "r"(b0), "r"(b1));
}
__device__ __forceinline__ void cp_async16(uint32_t dst, const void* src) {
    asm volatile("cp.async.cg.shared.global [%0], [%1], 16;"
                 :: "r"(dst), "l"(src) : "memory");
}
#define CP_COMMIT() asm volatile("cp.async.commit_group;" ::: "memory")
#define CP_WAIT0()  asm volatile("cp.async.wait_group 0;" ::: "memory")

__device__ __forceinline__ void split_pair(float v0, float v1,
                                           uint32_t& hiP, uint32_t& loP) {
    __nv_bfloat16 h0 = __float2bfloat16(v0), h1 = __float2bfloat16(v1);
    float r0 = v0 - __bfloat162float(h0);
    float r1 = v1 - __bfloat162float(h1);
    __nv_bfloat16 l0 = __float2bfloat16(r0), l1 = __float2bfloat16(r1);
    __nv_bfloat162 hp = __halves2bfloat162(h0, h1);
    __nv_bfloat162 lp = __halves2bfloat162(l0, l1);
    hiP = *(uint32_t*)&hp;
    loP = *(uint32_t*)&lp;
}

// w-pair: leaky+exp+mask, bf16 hi/lo split, rowsum accumulate
__device__ __forceinline__ void make_w_pair(float s1v, int a0, int a1,
                                            float s20, float s21,
                                            float& lsum, uint32_t& hiP, uint32_t& loP)
{
    float x0 = s1v + s20; x0 = fmaxf(x0, ALPHA * x0);
    float x1 = s1v + s21; x1 = fmaxf(x1, ALPHA * x1);
    float w0 = (a0 > 0) ? __expf(x0) : 0.f;
    float w1 = (a1 > 0) ? __expf(x1) : 0.f;
    lsum += w0 + w1;
    split_pair(w0, w1, hiP, loP);
}

// ---------------------------------------------------------------------------
// Kernel 0: split W (256x256 fp32, [out][k]) into bf16 hi/lo. Grid 32 x 256.
// ---------------------------------------------------------------------------
__global__ void __launch_bounds__(256) k0_convW(const float* __restrict__ Ww)
{
    int idx = (blockIdx.x * 256 + threadIdx.x) * 8;
    float4 v0 = *(const float4*)(Ww + idx);
    float4 v1 = *(const float4*)(Ww + idx + 4);
    float xs[8] = {v0.x, v0.y, v0.z, v0.w, v1.x, v1.y, v1.z, v1.w};
    uint32_t hw[4], lw[4];
#pragma unroll
    for (int e = 0; e < 8; e += 2) split_pair(xs[e], xs[e + 1], hw[e >> 1], lw[e >> 1]);
    *(uint4*)(gW_hi + idx) = make_uint4(hw[0], hw[1], hw[2], hw[3]);
    *(uint4*)(gW_lo + idx) = make_uint4(lw[0], lw[1], lw[2], lw[3]);
}

// ---------------------------------------------------------------------------
// Shared tile constants (k1_hmma and k2 use the same skeleton)
// ---------------------------------------------------------------------------
#define KC2   32
#define AST   40
#define BST   40
#define A_BYTES (128 * AST * 2)           // 10240
#define B_BYTES (256 * BST * 2)           // 20480
#define STAGE   (2 * A_BYTES + 2 * B_BYTES)   // 61440
#define DYN_SMEM (2 * STAGE)                  // 122880

// ---------------------------------------------------------------------------
// Kernel 1: HMMA Wh = h @ W^T (+bias, s1/s2 in epilogue), bf16 3-term split.
//   CTA 128 rows x 256 out, 512 thr, 8 k-chunks of 32. Writes g_Wh fp32.
// ---------------------------------------------------------------------------
__global__ void __launch_bounds__(512, 1) k1_hmma(
    const float* __restrict__ h,  const float* __restrict__ Wb,
    const float* __restrict__ aiw, const float* __restrict__ aib,
    const float* __restrict__ ajw, const float* __restrict__ ajb)
{
    extern __shared__ __align__(16) char smRaw[];
    __shared__ float sWb[F_], sAi[F_], sAj[F_];
    __shared__ float red1[128][4], red2[128][4];

    const int t    = threadIdx.x;
    const int lane = t & 31;
    const int wid  = t >> 5;
    const int wm   = wid & 3;
    const int wn   = wid >> 2;
    const int row0 = blockIdx.x * 128;

    const uint32_t smBase = smem_u32(smRaw);

    if (t < F_) { sWb[t] = Wb[t]; sAi[t] = aiw[t]; sAj[t] = ajw[t]; }

    // ---- roles (identical to k2) ----
    const int ig = t >> 2;                   // A row 0..127
    const int jg = (t & 3) * 8;              // 8-k subgroup
    const int fB = t >> 1;                   // B row (out) 0..255
    const int hB = (t & 1) * 16;

    const float* hP = h + (size_t)(row0 + ig) * F_;
    const __nv_bfloat16* wHiP = gW_hi + fB * F_;
    const __nv_bfloat16* wLoP = gW_lo + fB * F_;

    float acc[2][8][4];
#pragma unroll
    for (int m = 0; m < 2; m++)
#pragma unroll
        for (int n = 0; n < 8; n++)
#pragma unroll
            for (int q = 0; q < 4; q++) acc[m][n][q] = 0.f;

    uint32_t hw[4], lw[4];

    // ---- prologue: A(0) from h, B(0) via cp.async ----
    {
        float4 v0 = *(const float4*)(hP + jg);
        float4 v1 = *(const float4*)(hP + jg + 4);
        split_pair(v0.x, v0.y, hw[0], lw[0]);
        split_pair(v0.z, v0.w, hw[1], lw[1]);
        split_pair(v1.x, v1.y, hw[2], lw[2]);
        split_pair(v1.z, v1.w, hw[3], lw[3]);

        uint32_t dH = smBase + 2 * A_BYTES + (uint32_t)(fB * BST + hB) * 2u;
        cp_async16(dH,      wHiP + hB);
        cp_async16(dH + 16, wHiP + hB + 8);
        cp_async16(dH + B_BYTES,      wLoP + hB);
        cp_async16(dH + B_BYTES + 16, wLoP + hB + 8);
        CP_COMMIT();

        uint32_t off = (uint32_t)(ig * AST + jg) * 2u;
        asm volatile("st.shared.v4.b32 [%0], {%1,%2,%3,%4};"
                     :: "r"(smBase + off), "r"(hw[0]), "r"(hw[1]), "r"(hw[2]), "r"(hw[3]));
        asm volatile("st.shared.v4.b32 [%0], {%1,%2,%3,%4};"
                     :: "r"(smBase + A_BYTES + off), "r"(lw[0]), "r"(lw[1]), "r"(lw[2]), "r"(lw[3]));
        CP_WAIT0();
    }
    __syncthreads();

    for (int c = 0; c < 8; ++c) {
        const uint32_t sb   = smBase + (c & 1) * STAGE;
        const uint32_t sbN  = smBase + ((c + 1) & 1) * STAGE;
        const uint32_t aHiS = sb;
        const uint32_t aLoS = sb + A_BYTES;
        const uint32_t bHiS = sb + 2 * A_BYTES;
        const uint32_t bLoS = bHiS + B_BYTES;
        const bool doNext = (c + 1 < 8);
        const int  kn = (c + 1) * KC2;

        float4 ph0, ph1;
        if (doNext) {
            uint32_t dH = sbN + 2 * A_BYTES + (uint32_t)(fB * BST + hB) * 2u;
            cp_async16(dH,      wHiP + kn + hB);
            cp_async16(dH + 16, wHiP + kn + hB + 8);
            cp_async16(dH + B_BYTES,      wLoP + kn + hB);
            cp_async16(dH + B_BYTES + 16, wLoP + kn + hB + 8);
            CP_COMMIT();
            ph0 = *(const float4*)(hP + kn + jg);
            ph1 = *(const float4*)(hP + kn + jg + 4);
        }

        // ---- MMA(c): identical structure to k2 ----
#pragma unroll
        for (int ks = 0; ks < 2; ++ks) {
            const int k0 = ks * 16;
            uint32_t ah[2][4], al[2][4];
#pragma unroll
            for (int mt = 0; mt < 2; ++mt) {
                int arow = wm * 32 + mt * 16 + (lane & 15);
                uint32_t aoff = (uint32_t)(arow * AST + k0 + ((lane >> 4) << 3)) * 2u;
                ldm_x4(ah[mt][0], ah[mt][1], ah[mt][2], ah[mt][3], aHiS + aoff);
                ldm_x4(al[mt][0], al[mt][1], al[mt][2], al[mt][3], aLoS + aoff);
            }
#pragma unroll
            for (int pr = 0; pr < 4; ++pr) {
                int n0   = wn * 64 + pr * 16;
                int rowB = n0 + (lane & 7) + ((lane >> 4) << 3);
                int colB = k0 + (((lane >> 3) & 1) << 3);
                uint32_t boff = (uint32_t)(rowB * BST + colB) * 2u;
                uint32_t bh0, bh1, bh2, bh3, bl0, bl1, bl2, bl3;
                ldm_x4(bh0, bh1, bh2, bh3, bHiS + boff);
                ldm_x4(bl0, bl1, bl2, bl3, bLoS + boff);
                mma_bf16(acc[0][pr * 2],     ah[0], bh0, bh1);
                mma_bf16(acc[1][pr * 2],     ah[1], bh0, bh1);
                mma_bf16(acc[0][pr * 2 + 1], ah[0], bh2, bh3);
                mma_bf16(acc[1][pr * 2 + 1], ah[1], bh2, bh3);
                mma_bf16(acc[0][pr * 2],     ah[0], bl0, bl1);
                mma_bf16(acc[1][pr * 2],     ah[1], bl0, bl1);
                mma_bf16(acc[0][pr * 2 + 1], ah[0], bl2, bl3);
                mma_bf16(acc[1][pr * 2 + 1], ah[1], bl2, bl3);
                mma_bf16(acc[0][pr * 2],     al[0], bh0, bh1);
                mma_bf16(acc[1][pr * 2],     al[1], bh0, bh1);
                mma_bf16(acc[0][pr * 2 + 1], al[0], bh2, bh3);
                mma_bf16(acc[1][pr * 2 + 1], al[1], bh2, bh3);
            }
        }

        if (doNext) {
            split_pair(ph0.x, ph0.y, hw[0], lw[0]);
            split_pair(ph0.z, ph0.w, hw[1], lw[1]);
            split_pair(ph1.x, ph1.y, hw[2], lw[2]);
            split_pair(ph1.z, ph1.w, hw[3], lw[3]);
            uint32_t off = (uint32_t)(ig * AST + jg) * 2u;
            asm volatile("st.shared.v4.b32 [%0], {%1,%2,%3,%4};"
                         :: "r"(sbN + off), "r"(hw[0]), "r"(hw[1]), "r"(hw[2]), "r"(hw[3]));
            asm volatile("st.shared.v4.b32 [%0], {%1,%2,%3,%4};"
                         :: "r"(sbN + A_BYTES + off), "r"(lw[0]), "r"(lw[1]), "r"(lw[2]), "r"(lw[3]));
            CP_WAIT0();
        }
        __syncthreads();
    }

    // ---- epilogue: bias, s1/s2 reduction, Wh fp32 store ----
    const int g  = lane >> 2;
    const int tq = lane & 3;
#pragma unroll
    for (int mt = 0; mt < 2; ++mt) {
        int r0l = wm * 32 + mt * 16 + g;
        int r1l = r0l + 8;
        float a1_0 = 0.f, a2_0 = 0.f, a1_1 = 0.f, a2_1 = 0.f;
#pragma unroll
        for (int nt = 0; nt < 8; ++nt) {
            int col = wn * 64 + nt * 8 + 2 * tq;
            float b0 = sWb[col], b1 = sWb[col + 1];
            float i0v = sAi[col], i1v = sAi[col + 1];
            float j0v = sAj[col], j1v = sAj[col + 1];
            acc[mt][nt][0] += b0; acc[mt][nt][1] += b1;
            acc[mt][nt][2] += b0; acc[mt][nt][3] += b1;
            a1_0 = fmaf(acc[mt][nt][0], i0v, fmaf(acc[mt][nt][1], i1v, a1_0));
            a2_0 = fmaf(acc[mt][nt][0], j0v, fmaf(acc[mt][nt][1], j1v, a2_0));
            a1_1 = fmaf(acc[mt][nt][2], i0v, fmaf(acc[mt][nt][3], i1v, a1_1));
            a2_1 = fmaf(acc[mt][nt][2], j0v, fmaf(acc[mt][nt][3], j1v, a2_1));
        }
#pragma unroll
        for (int off = 1; off <= 2; off <<= 1) {
            a1_0 += __shfl_xor_sync(0xffffffffu, a1_0, off);
            a2_0 += __shfl_xor_sync(0xffffffffu, a2_0, off);
            a1_1 += __shfl_xor_sync(0xffffffffu, a1_1, off);
            a2_1 += __shfl_xor_sync(0xffffffffu, a2_1, off);
        }
        if (tq == 0) {
            red1[r0l][wn] = a1_0; red2[r0l][wn] = a2_0;
            red1[r1l][wn] = a1_1; red2[r1l][wn] = a2_1;
        }
        size_t o0 = (size_t)(row0 + r0l) * F_;
        size_t o1 = (size_t)(row0 + r1l) * F_;
#pragma unroll
        for (int nt = 0; nt < 8; ++nt) {
            int col = wn * 64 + nt * 8 + 2 * tq;
            *(float2*)(g_Wh + o0 + col) = make_float2(acc[mt][nt][0], acc[mt][nt][1]);
            *(float2*)(g_Wh + o1 + col) = make_float2(acc[mt][nt][2], acc[mt][nt][3]);
        }
    }
    __syncthreads();
    if (t < 128) {
        g_s1[row0 + t] = red1[t][0] + red1[t][1] + red1[t][2] + red1[t][3] + aib[0];
        g_s2[row0 + t] = red2[t][0] + red2[t][1] + red2[t][2] + red2[t][3] + ajb[0];
    }
}

// ---------------------------------------------------------------------------
// Kernel 1t: transpose + bf16 hi/lo split: WhT[b][f][j] = Wh[b][j][f]
// ---------------------------------------------------------------------------
__global__ void __launch_bounds__(256) k1t_transpose()
{
    __shared__ float ts[64][65];
    const int t   = threadIdx.x;
    const int bt  = blockIdx.x;
    const int b   = bt >> 7;
    const int rem = bt & 127;
    const int r0  = (rem >> 2) * 64;
    const int f0  = (rem & 3) * 64;

    {
        const int rr = t >> 2;
        const int cg = (t & 3) * 16;
        const float* src = g_Wh + ((size_t)(b * N_ + r0 + rr)) * F_ + f0 + cg;
#pragma unroll
        for (int g = 0; g < 4; g++) {
            float4 v = *(const float4*)(src + g * 4);
            ts[rr][cg + g * 4 + 0] = v.x;
            ts[rr][cg + g * 4 + 1] = v.y;
            ts[rr][cg + g * 4 + 2] = v.z;
            ts[rr][cg + g * 4 + 3] = v.w;
        }
    }
    __syncthreads();

    const int f  = t >> 2;
    const int rb = (t & 3) * 16;
    uint32_t hp[8], lp[8];
#pragma unroll
    for (int e = 0; e < 16; e += 2)
        split_pair(ts[rb + e][f], ts[rb + e + 1][f], hp[e >> 1], lp[e >> 1]);
    size_t dst = ((size_t)(b * F_ + f0 + f)) * N_ + r0 + rb;
    uint4* dh = (uint4*)(g_WhT_hi + dst);
    uint4* dl = (uint4*)(g_WhT_lo + dst);
    dh[0] = make_uint4(hp[0], hp[1], hp[2], hp[3]);
    dh[1] = make_uint4(hp[4], hp[5], hp[6], hp[7]);
    dl[0] = make_uint4(lp[0], lp[1], lp[2], lp[3]);
    dl[1] = make_uint4(lp[4], lp[5], lp[6], lp[7]);
}

// ---------------------------------------------------------------------------
// Kernel 2: HMMA attention GEMM (R7 best: 512 thr, 128i x 256f, interleaved)
// ---------------------------------------------------------------------------
#define NCH2  (N_ / KC2)                  // 64 chunks

__global__ void __launch_bounds__(512, 1) k2_attn(
    const int* __restrict__ adj, float* __restrict__ out)
{
    extern __shared__ __align__(16) char smRaw[];
    __shared__ float s1S[128];
    __shared__ __align__(16) float s2S[N_];
    __shared__ float rsS[128][4];
    __shared__ float rInv[128];

    const int t    = threadIdx.x;
    const int lane = t & 31;
    const int wid  = t >> 5;
    const int wm   = wid & 3;
    const int wn   = wid >> 2;
    const int b    = blockIdx.x >> 4;
    const int i0   = (blockIdx.x & 15) * 128;

    const uint32_t smBase = smem_u32(smRaw);

    if (t < 128) s1S[t] = g_s1[b * N_ + i0 + t];
    {
        const float4* s2g = (const float4*)(g_s2 + b * N_);
#pragma unroll
        for (int k = t; k < N_ / 4; k += 512) ((float4*)s2S)[k] = s2g[k];
    }

    const int ig = t >> 2;
    const int jg = (t & 3) * 8;
    const int fB = t >> 1;
    const int hB = (t & 1) * 16;

    const int* adjP = adj + (size_t)(b * N_ + i0 + ig) * N_;
    const __nv_bfloat16* bhP = g_WhT_hi + (size_t)(b * F_ + fB) * N_;
    const __nv_bfloat16* blP = g_WhT_lo + (size_t)(b * F_ + fB) * N_;

    float acc[2][8][4];
#pragma unroll
    for (int m = 0; m < 2; m++)
#pragma unroll
        for (int n = 0; n < 8; n++)
#pragma unroll
            for (int q = 0; q < 4; q++) acc[m][n][q] = 0.f;
    float lsum = 0.f;

    uint32_t hw[4], lw[4];

    __syncthreads();

    {
        int4 a0 = *(const int4*)(adjP + jg);
        int4 a1 = *(const int4*)(adjP + jg + 4);
        const float s1v = s1S[ig];
        make_w_pair(s1v, a0.x, a0.y, s2S[jg + 0], s2S[jg + 1], lsum, hw[0], lw[0]);
        make_w_pair(s1v, a0.z, a0.w, s2S[jg + 2], s2S[jg + 3], lsum, hw[1], lw[1]);
        make_w_pair(s1v, a1.x, a1.y, s2S[jg + 4], s2S[jg + 5], lsum, hw[2], lw[2]);
        make_w_pair(s1v, a1.z, a1.w, s2S[jg + 6], s2S[jg + 7], lsum, hw[3], lw[3]);

        uint32_t dH = smBase + 2 * A_BYTES + (uint32_t)(fB * BST + hB) * 2u;
        cp_async16(dH,      bhP + hB);
        cp_async16(dH + 16, bhP + hB + 8);
        cp_async16(dH + B_BYTES,      blP + hB);
        cp_async16(dH + B_BYTES + 16, blP + hB + 8);
        CP_COMMIT();

        uint32_t off = (uint32_t)(ig * AST + jg) * 2u;
        asm volatile("st.shared.v4.b32 [%0], {%1,%2,%3,%4};"
                     :: "r"(smBase + off), "r"(hw[0]), "r"(hw[1]), "r"(hw[2]), "r"(hw[3]));
        asm volatile("st.shared.v4.b32 [%0], {%1,%2,%3,%4};"
                     :: "r"(smBase + A_BYTES + off), "r"(lw[0]), "r"(lw[1]), "r"(lw[2]), "r"(lw[3]));
        CP_WAIT0();
    }
    __syncthreads();

    for (int c = 0; c < NCH2; ++c) {
        const uint32_t sb   = smBase + (c & 1) * STAGE;
        const uint32_t sbN  = smBase + ((c + 1) & 1) * STAGE;
        const uint32_t aHiS = sb;
        const uint32_t aLoS = sb + A_BYTES;
        const uint32_t bHiS = sb + 2 * A_BYTES;
        const uint32_t bLoS = bHiS + B_BYTES;
        const bool doNext = (c + 1 < NCH2);
        const int  jn = (c + 1) * KC2;

        int4 pA0, pA1;
        if (doNext) {
            uint32_t dH = sbN + 2 * A_BYTES + (uint32_t)(fB * BST + hB) * 2u;
            cp_async16(dH,      bhP + jn + hB);
            cp_async16(dH + 16, bhP + jn + hB + 8);
            cp_async16(dH + B_BYTES,      blP + jn + hB);
            cp_async16(dH + B_BYTES + 16, blP + jn + hB + 8);
            CP_COMMIT();
            pA0 = *(const int4*)(adjP + jn + jg);
            pA1 = *(const int4*)(adjP + jn + jg + 4);
        }
        const float s1v = s1S[ig];

#pragma unroll
        for (int ks = 0; ks < 2; ++ks) {
            const int k0 = ks * 16;
            uint32_t ah[2][4], al[2][4];
#pragma unroll
            for (int mt = 0; mt < 2; ++mt) {
                int arow = wm * 32 + mt * 16 + (lane & 15);
                uint32_t aoff = (uint32_t)(arow * AST + k0 + ((lane >> 4) << 3)) * 2u;
                ldm_x4(ah[mt][0], ah[mt][1], ah[mt][2], ah[mt][3], aHiS + aoff);
                ldm_x4(al[mt][0], al[mt][1], al[mt][2], al[mt][3], aLoS + aoff);
            }
#pragma unroll
            for (int pr = 0; pr < 4; ++pr) {
                int n0   = wn * 64 + pr * 16;
                int rowB = n0 + (lane & 7) + ((lane >> 4) << 3);
                int colB = k0 + (((lane >> 3) & 1) << 3);
                uint32_t boff = (uint32_t)(rowB * BST + colB) * 2u;
                uint32_t bh0, bh1, bh2, bh3, bl0, bl1, bl2, bl3;
                ldm_x4(bh0, bh1, bh2, bh3, bHiS + boff);
                ldm_x4(bl0, bl1, bl2, bl3, bLoS + boff);
                mma_bf16(acc[0][pr * 2],     ah[0], bh0, bh1);
                mma_bf16(acc[1][pr * 2],     ah[1], bh0, bh1);
                mma_bf16(acc[0][pr * 2 + 1], ah[0], bh2, bh3);
                mma_bf16(acc[1][pr * 2 + 1], ah[1], bh2, bh3);
                mma_bf16(acc[0][pr * 2],     ah[0], bl0, bl1);
                mma_bf16(acc[1][pr * 2],     ah[1], bl0, bl1);
                mma_bf16(acc[0][pr * 2 + 1], ah[0], bl2, bl3);
                mma_bf16(acc[1][pr * 2 + 1], ah[1], bl2, bl3);
                mma_bf16(acc[0][pr * 2],     al[0], bh0, bh1);
                mma_bf16(acc[1][pr * 2],     al[1], bh0, bh1);
                mma_bf16(acc[0][pr * 2 + 1], al[0], bh2, bh3);
                mma_bf16(acc[1][pr * 2 + 1], al[1], bh2, bh3);

                if (doNext && ks == 1) {
                    int a0 = (pr < 2) ? ((pr == 0) ? pA0.x : pA0.z)
                                      : ((pr == 2) ? pA1.x : pA1.z);
                    int a1 = (pr < 2) ? ((pr == 0) ? pA0.y : pA0.w)
                                      : ((pr == 2) ? pA1.y : pA1.w);
                    make_w_pair(s1v, a0, a1,
                                s2S[jn + jg + 2 * pr], s2S[jn + jg + 2 * pr + 1],
                                lsum, hw[pr], lw[pr]);
                }
            }
        }

        if (doNext) {
            uint32_t off = (uint32_t)(ig * AST + jg) * 2u;
            asm volatile("st.shared.v4.b32 [%0], {%1,%2,%3,%4};"
                         :: "r"(sbN + off), "r"(hw[0]), "r"(hw[1]), "r"(hw[2]), "r"(hw[3]));
            asm volatile("st.shared.v4.b32 [%0], {%1,%2,%3,%4};"
                         :: "r"(sbN + A_BYTES + off), "r"(lw[0]), "r"(lw[1]), "r"(lw[2]), "r"(lw[3]));
            CP_WAIT0();
        }
        __syncthreads();
    }

    rsS[ig][t & 3] = lsum;
    __syncthreads();
    if (t < 128) rInv[t] = 1.f / (rsS[t][0] + rsS[t][1] + rsS[t][2] + rsS[t][3]);
    __syncthreads();

    const int g  = lane >> 2;
    const int tq = lane & 3;
#pragma unroll
    for (int mt = 0; mt < 2; ++mt) {
        int r0l = wm * 32 + mt * 16 + g;
        int r1l = r0l + 8;
        float inv0 = rInv[r0l], inv1 = rInv[r1l];
        size_t o0 = ((size_t)(b * N_ + i0 + r0l)) * F_;
        size_t o1 = ((size_t)(b * N_ + i0 + r1l)) * F_;
#pragma unroll
        for (int nt = 0; nt < 8; ++nt) {
            int col = wn * 64 + nt * 8 + 2 * tq;
            float x0 = acc[mt][nt][0] * inv0;
            float x1 = acc[mt][nt][1] * inv0;
            float x2 = acc[mt][nt][2] * inv1;
            float x3 = acc[mt][nt][3] * inv1;
            x0 = (x0 > 0.f) ? x0 : expm1f(x0);
            x1 = (x1 > 0.f) ? x1 : expm1f(x1);
            x2 = (x2 > 0.f) ? x2 : expm1f(x2);
            x3 = (x3 > 0.f) ? x3 : expm1f(x3);
            *(float2*)(out + o0 + col) = make_float2(x0, x1);
            *(float2*)(out + o1 + col) = make_float2(x2, x3);
        }
    }
}

// ---------------------------------------------------------------------------
extern "C" void kernel_launch(void* const* d_in, const int* in_sizes, int n_in,
                              void* d_out, int out_size)
{
    const float* h   = (const float*)d_in[0];
    const int*   adj = (const int*)  d_in[1];
    const float* Ww  = (const float*)d_in[2];
    const float* Wb  = (const float*)d_in[3];
    const float* aiw = (const float*)d_in[4];
    const float* aib = (const float*)d_in[5];
    const float* ajw = (const float*)d_in[6];
    const float* ajb = (const float*)d_in[7];
    float* out = (float*)d_out;

    static bool attrDone = false;
    if (!attrDone) {
        cudaFuncSetAttribute(k1_hmma, cudaFuncAttributeMaxDynamicSharedMemorySize,
                             DYN_SMEM);
        cudaFuncSetAttribute(k2_attn, cudaFuncAttributeMaxDynamicSharedMemorySize,
                             DYN_SMEM);
        attrDone = true;
    }

    k0_convW<<<32, 256>>>(Ww);
    k1_hmma<<<(B_ * N_) / 128, 512, DYN_SMEM>>>(h, Wb, aiw, aib, ajw, ajb);
    k1t_transpose<<<B_ * 128, 256>>>();
    k2_attn<<<B_ * (N_ / 128), 512, DYN_SMEM>>>(adj, out);
}

// round 11
// speedup vs baseline: 1.5927x; 1.0034x over previous
#include <cuda_runtime.h>
#include <cuda_bf16.h>
#include <math.h>
#include <cstdint>
#include <cstddef>

#define B_   8
#define N_   2048
#define F_   256
#define ALPHA 0.2f

// ---------------- device scratch (allocation-free rule) ----------------
__device__ float g_s1[B_ * N_];
__device__ float g_s2[B_ * N_];
__device__ __nv_bfloat16 g_WhT_hi[B_ * F_ * N_];   // [b][f][j]
__device__ __nv_bfloat16 g_WhT_lo[B_ * F_ * N_];
__device__ __nv_bfloat16 gW_hi[F_ * F_];           // W split, [out][k]
__device__ __nv_bfloat16 gW_lo[F_ * F_];

__device__ __forceinline__ uint32_t smem_u32(const void* p) {
    uint32_t a;
    asm("{ .reg .u64 t; cvta.to.shared.u64 t, %1; cvt.u32.u64 %0, t; }"
        : "=r"(a) : "l"(p));
    return a;
}
__device__ __forceinline__ void ldm_x4(uint32_t& r0, uint32_t& r1,
                                       uint32_t& r2, uint32_t& r3, uint32_t addr) {
    asm volatile("ldmatrix.sync.aligned.m8n8.x4.shared.b16 {%0,%1,%2,%3}, [%4];"
                 : "=r"(r0), "=r"(r1), "=r"(r2), "=r"(r3) : "r"(addr));
}
__device__ __forceinline__ void mma_bf16(float* d, const uint32_t* a,
                                         uint32_t b0, uint32_t b1) {
    asm volatile(
        "mma.sync.aligned.m16n8k16.row.col.f32.bf16.bf16.f32 "
        "{%0,%1,%2,%3}, {%4,%5,%6,%7}, {%8,%9}, {%0,%1,%2,%3};"
        : "+f"(d[0]), "+f"(d[1]), "+f"(d[2]), "+f"(d[3])
        : "r"(a[0]), "r"(a[1]), "r"(a[2]), "r"(a[3]), "r"(b0), "r"(b1));
}
__device__ __forceinline__ void cp_async16(uint32_t dst, const void* src) {
    asm volatile("cp.async.cg.shared.global [%0], [%1], 16;"
                 :: "r"(dst), "l"(src) : "memory");
}
#define CP_COMMIT() asm volatile("cp.async.commit_group;" ::: "memory")
#define CP_WAIT0()  asm volatile("cp.async.wait_group 0;" ::: "memory")

__device__ __forceinline__ void split_pair(float v0, float v1,
                                           uint32_t& hiP, uint32_t& loP) {
    __nv_bfloat16 h0 = __float2bfloat16(v0), h1 = __float2bfloat16(v1);
    float r0 = v0 - __bfloat162float(h0);
    float r1 = v1 - __bfloat162float(h1);
    __nv_bfloat16 l0 = __float2bfloat16(r0), l1 = __float2bfloat16(r1);
    __nv_bfloat162 hp = __halves2bfloat162(h0, h1);
    __nv_bfloat162 lp = __halves2bfloat162(l0, l1);
    hiP = *(uint32_t*)&hp;
    loP = *(uint32_t*)&lp;
}

// w-pair: leaky+exp+mask, bf16 hi/lo split, rowsum accumulate
__device__ __forceinline__ void make_w_pair(float s1v, int a0, int a1,
                                            float s20, float s21,
                                            float& lsum, uint32_t& hiP, uint32_t& loP)
{
    float x0 = s1v + s20; x0 = fmaxf(x0, ALPHA * x0);
    float x1 = s1v + s21; x1 = fmaxf(x1, ALPHA * x1);
    float w0 = (a0 > 0) ? __expf(x0) : 0.f;
    float w1 = (a1 > 0) ? __expf(x1) : 0.f;
    lsum += w0 + w1;
    split_pair(w0, w1, hiP, loP);
}

// ---------------------------------------------------------------------------
// Kernel 0: split W (256x256 fp32, [out][k]) into bf16 hi/lo. Grid 32 x 256.
// ---------------------------------------------------------------------------
__global__ void __launch_bounds__(256) k0_convW(const float* __restrict__ Ww)
{
    int idx = (blockIdx.x * 256 + threadIdx.x) * 8;
    float4 v0 = *(const float4*)(Ww + idx);
    float4 v1 = *(const float4*)(Ww + idx + 4);
    float xs[8] = {v0.x, v0.y, v0.z, v0.w, v1.x, v1.y, v1.z, v1.w};
    uint32_t hw[4], lw[4];
#pragma unroll
    for (int e = 0; e < 8; e += 2) split_pair(xs[e], xs[e + 1], hw[e >> 1], lw[e >> 1]);
    *(uint4*)(gW_hi + idx) = make_uint4(hw[0], hw[1], hw[2], hw[3]);
    *(uint4*)(gW_lo + idx) = make_uint4(lw[0], lw[1], lw[2], lw[3]);
}

// ---------------------------------------------------------------------------
// Shared tile constants (k1_hmma and k2 use the same skeleton)
// ---------------------------------------------------------------------------
#define KC2   32
#define AST   40
#define BST   40
#define A_BYTES (128 * AST * 2)           // 10240
#define B_BYTES (256 * BST * 2)           // 20480
#define STAGE   (2 * A_BYTES + 2 * B_BYTES)   // 61440
#define DYN_SMEM (2 * STAGE)                  // 122880

// ---------------------------------------------------------------------------
// Kernel 1: HMMA Wh = h @ W^T (+bias, s1/s2), bf16 3-term split.
//   CTA 128 rows x 256 out, 512 thr, 8 k-chunks of 32.
//   FUSED epilogue: stages the output tile in smem (2 x 128f passes) and
//   writes WhT hi/lo directly (transpose+split) — no g_Wh round-trip.
// ---------------------------------------------------------------------------
__global__ void __launch_bounds__(512, 1) k1_hmma(
    const float* __restrict__ h,  const float* __restrict__ Wb,
    const float* __restrict__ aiw, const float* __restrict__ aib,
    const float* __restrict__ ajw, const float* __restrict__ ajb)
{
    extern __shared__ __align__(16) char smRaw[];
    __shared__ float sWb[F_], sAi[F_], sAj[F_];
    __shared__ float red1[128][4], red2[128][4];

    const int t    = threadIdx.x;
    const int lane = t & 31;
    const int wid  = t >> 5;
    const int wm   = wid & 3;
    const int wn   = wid >> 2;
    const int row0 = blockIdx.x * 128;

    const uint32_t smBase = smem_u32(smRaw);

    if (t < F_) { sWb[t] = Wb[t]; sAi[t] = aiw[t]; sAj[t] = ajw[t]; }

    // ---- roles (identical to k2) ----
    const int ig = t >> 2;                   // A row 0..127
    const int jg = (t & 3) * 8;              // 8-k subgroup
    const int fB = t >> 1;                   // B row (out) 0..255
    const int hB = (t & 1) * 16;

    const float* hP = h + (size_t)(row0 + ig) * F_;
    const __nv_bfloat16* wHiP = gW_hi + fB * F_;
    const __nv_bfloat16* wLoP = gW_lo + fB * F_;

    float acc[2][8][4];
#pragma unroll
    for (int m = 0; m < 2; m++)
#pragma unroll
        for (int n = 0; n < 8; n++)
#pragma unroll
            for (int q = 0; q < 4; q++) acc[m][n][q] = 0.f;

    uint32_t hw[4], lw[4];

    // ---- prologue: A(0) from h, B(0) via cp.async ----
    {
        float4 v0 = *(const float4*)(hP + jg);
        float4 v1 = *(const float4*)(hP + jg + 4);
        split_pair(v0.x, v0.y, hw[0], lw[0]);
        split_pair(v0.z, v0.w, hw[1], lw[1]);
        split_pair(v1.x, v1.y, hw[2], lw[2]);
        split_pair(v1.z, v1.w, hw[3], lw[3]);

        uint32_t dH = smBase + 2 * A_BYTES + (uint32_t)(fB * BST + hB) * 2u;
        cp_async16(dH,      wHiP + hB);
        cp_async16(dH + 16, wHiP + hB + 8);
        cp_async16(dH + B_BYTES,      wLoP + hB);
        cp_async16(dH + B_BYTES + 16, wLoP + hB + 8);
        CP_COMMIT();

        uint32_t off = (uint32_t)(ig * AST + jg) * 2u;
        asm volatile("st.shared.v4.b32 [%0], {%1,%2,%3,%4};"
                     :: "r"(smBase + off), "r"(hw[0]), "r"(hw[1]), "r"(hw[2]), "r"(hw[3]));
        asm volatile("st.shared.v4.b32 [%0], {%1,%2,%3,%4};"
                     :: "r"(smBase + A_BYTES + off), "r"(lw[0]), "r"(lw[1]), "r"(lw[2]), "r"(lw[3]));
        CP_WAIT0();
    }
    __syncthreads();

    for (int c = 0; c < 8; ++c) {
        const uint32_t sb   = smBase + (c & 1) * STAGE;
        const uint32_t sbN  = smBase + ((c + 1) & 1) * STAGE;
        const uint32_t aHiS = sb;
        const uint32_t aLoS = sb + A_BYTES;
        const uint32_t bHiS = sb + 2 * A_BYTES;
        const uint32_t bLoS = bHiS + B_BYTES;
        const bool doNext = (c + 1 < 8);
        const int  kn = (c + 1) * KC2;

        float4 ph0, ph1;
        if (doNext) {
            uint32_t dH = sbN + 2 * A_BYTES + (uint32_t)(fB * BST + hB) * 2u;
            cp_async16(dH,      wHiP + kn + hB);
            cp_async16(dH + 16, wHiP + kn + hB + 8);
            cp_async16(dH + B_BYTES,      wLoP + kn + hB);
            cp_async16(dH + B_BYTES + 16, wLoP + kn + hB + 8);
            CP_COMMIT();
            ph0 = *(const float4*)(hP + kn + jg);
            ph1 = *(const float4*)(hP + kn + jg + 4);
        }

        // ---- MMA(c) ----
#pragma unroll
        for (int ks = 0; ks < 2; ++ks) {
            const int k0 = ks * 16;
            uint32_t ah[2][4], al[2][4];
#pragma unroll
            for (int mt = 0; mt < 2; ++mt) {
                int arow = wm * 32 + mt * 16 + (lane & 15);
                uint32_t aoff = (uint32_t)(arow * AST + k0 + ((lane >> 4) << 3)) * 2u;
                ldm_x4(ah[mt][0], ah[mt][1], ah[mt][2], ah[mt][3], aHiS + aoff);
                ldm_x4(al[mt][0], al[mt][1], al[mt][2], al[mt][3], aLoS + aoff);
            }
#pragma unroll
            for (int pr = 0; pr < 4; ++pr) {
                int n0   = wn * 64 + pr * 16;
                int rowB = n0 + (lane & 7) + ((lane >> 4) << 3);
                int colB = k0 + (((lane >> 3) & 1) << 3);
                uint32_t boff = (uint32_t)(rowB * BST + colB) * 2u;
                uint32_t bh0, bh1, bh2, bh3, bl0, bl1, bl2, bl3;
                ldm_x4(bh0, bh1, bh2, bh3, bHiS + boff);
                ldm_x4(bl0, bl1, bl2, bl3, bLoS + boff);
                mma_bf16(acc[0][pr * 2],     ah[0], bh0, bh1);
                mma_bf16(acc[1][pr * 2],     ah[1], bh0, bh1);
                mma_bf16(acc[0][pr * 2 + 1], ah[0], bh2, bh3);
                mma_bf16(acc[1][pr * 2 + 1], ah[1], bh2, bh3);
                mma_bf16(acc[0][pr * 2],     ah[0], bl0, bl1);
                mma_bf16(acc[1][pr * 2],     ah[1], bl0, bl1);
                mma_bf16(acc[0][pr * 2 + 1], ah[0], bl2, bl3);
                mma_bf16(acc[1][pr * 2 + 1], ah[1], bl2, bl3);
                mma_bf16(acc[0][pr * 2],     al[0], bh0, bh1);
                mma_bf16(acc[1][pr * 2],     al[1], bh0, bh1);
                mma_bf16(acc[0][pr * 2 + 1], al[0], bh2, bh3);
                mma_bf16(acc[1][pr * 2 + 1], al[1], bh2, bh3);
            }
        }

        if (doNext) {
            split_pair(ph0.x, ph0.y, hw[0], lw[0]);
            split_pair(ph0.z, ph0.w, hw[1], lw[1]);
            split_pair(ph1.x, ph1.y, hw[2], lw[2]);
            split_pair(ph1.z, ph1.w, hw[3], lw[3]);
            uint32_t off = (uint32_t)(ig * AST + jg) * 2u;
            asm volatile("st.shared.v4.b32 [%0], {%1,%2,%3,%4};"
                         :: "r"(sbN + off), "r"(hw[0]), "r"(hw[1]), "r"(hw[2]), "r"(hw[3]));
            asm volatile("st.shared.v4.b32 [%0], {%1,%2,%3,%4};"
                         :: "r"(sbN + A_BYTES + off), "r"(lw[0]), "r"(lw[1]), "r"(lw[2]), "r"(lw[3]));
            CP_WAIT0();
        }
        __syncthreads();
    }

    // ---- epilogue part 1: bias, s1/s2 reduction ----
    const int g  = lane >> 2;
    const int tq = lane & 3;
#pragma unroll
    for (int mt = 0; mt < 2; ++mt) {
        int r0l = wm * 32 + mt * 16 + g;
        int r1l = r0l + 8;
        float a1_0 = 0.f, a2_0 = 0.f, a1_1 = 0.f, a2_1 = 0.f;
#pragma unroll
        for (int nt = 0; nt < 8; ++nt) {
            int col = wn * 64 + nt * 8 + 2 * tq;
            float b0 = sWb[col], b1 = sWb[col + 1];
            float i0v = sAi[col], i1v = sAi[col + 1];
            float j0v = sAj[col], j1v = sAj[col + 1];
            acc[mt][nt][0] += b0; acc[mt][nt][1] += b1;
            acc[mt][nt][2] += b0; acc[mt][nt][3] += b1;
            a1_0 = fmaf(acc[mt][nt][0], i0v, fmaf(acc[mt][nt][1], i1v, a1_0));
            a2_0 = fmaf(acc[mt][nt][0], j0v, fmaf(acc[mt][nt][1], j1v, a2_0));
            a1_1 = fmaf(acc[mt][nt][2], i0v, fmaf(acc[mt][nt][3], i1v, a1_1));
            a2_1 = fmaf(acc[mt][nt][2], j0v, fmaf(acc[mt][nt][3], j1v, a2_1));
        }
#pragma unroll
        for (int off = 1; off <= 2; off <<= 1) {
            a1_0 += __shfl_xor_sync(0xffffffffu, a1_0, off);
            a2_0 += __shfl_xor_sync(0xffffffffu, a2_0, off);
            a1_1 += __shfl_xor_sync(0xffffffffu, a1_1, off);
            a2_1 += __shfl_xor_sync(0xffffffffu, a2_1, off);
        }
        if (tq == 0) {
            red1[r0l][wn] = a1_0; red2[r0l][wn] = a2_0;
            red1[r1l][wn] = a1_1; red2[r1l][wn] = a2_1;
        }
    }
    __syncthreads();
    if (t < 128) {
        g_s1[row0 + t] = red1[t][0] + red1[t][1] + red1[t][2] + red1[t][3] + aib[0];
        g_s2[row0 + t] = red2[t][0] + red2[t][1] + red2[t][2] + red2[t][3] + ajb[0];
    }

    // ---- epilogue part 2: FUSED transpose + bf16 split, two 128f passes ----
    // Staging tile: 128 rows x 132 stride fp32 in dynamic smem (67.6 KB).
    float* ts = (float*)smRaw;
    const int b   = row0 >> 11;
    const int jlo = row0 & (N_ - 1);
    const int fLoc = t >> 2;                 // 0..127
    const int jseg = (t & 3) * 32;           // 0,32,64,96

#pragma unroll
    for (int fh = 0; fh < 2; ++fh) {
        __syncthreads();                     // previous pass reads / mainloop done
        if ((wn >> 1) == fh) {
#pragma unroll
            for (int mt = 0; mt < 2; ++mt) {
                int r0l = wm * 32 + mt * 16 + g;
                int r1l = r0l + 8;
#pragma unroll
                for (int nt = 0; nt < 8; ++nt) {
                    int colL = (wn & 1) * 64 + nt * 8 + 2 * tq;
                    *(float2*)&ts[r0l * 132 + colL] =
                        make_float2(acc[mt][nt][0], acc[mt][nt][1]);
                    *(float2*)&ts[r1l * 132 + colL] =
                        make_float2(acc[mt][nt][2], acc[mt][nt][3]);
                }
            }
        }
        __syncthreads();
        // read column fLoc, rows jseg..jseg+31; split; store WhT hi/lo
        uint32_t hp[16], lp[16];
#pragma unroll
        for (int e = 0; e < 32; e += 2) {
            float v0 = ts[(jseg + e) * 132 + fLoc];
            float v1 = ts[(jseg + e + 1) * 132 + fLoc];
            split_pair(v0, v1, hp[e >> 1], lp[e >> 1]);
        }
        size_t dst = ((size_t)(b * F_ + fh * 128 + fLoc)) * N_ + jlo + jseg;
        uint4* dh = (uint4*)(g_WhT_hi + dst);
        uint4* dl = (uint4*)(g_WhT_lo + dst);
        dh[0] = make_uint4(hp[0],  hp[1],  hp[2],  hp[3]);
        dh[1] = make_uint4(hp[4],  hp[5],  hp[6],  hp[7]);
        dh[2] = make_uint4(hp[8],  hp[9],  hp[10], hp[11]);
        dh[3] = make_uint4(hp[12], hp[13], hp[14], hp[15]);
        dl[0] = make_uint4(lp[0],  lp[1],  lp[2],  lp[3]);
        dl[1] = make_uint4(lp[4],  lp[5],  lp[6],  lp[7]);
        dl[2] = make_uint4(lp[8],  lp[9],  lp[10], lp[11]);
        dl[3] = make_uint4(lp[12], lp[13], lp[14], lp[15]);
    }
}

// ---------------------------------------------------------------------------
// Kernel 2: HMMA attention GEMM (R7/R10 best: 512 thr, 128i x 256f)
// ---------------------------------------------------------------------------
#define NCH2  (N_ / KC2)                  // 64 chunks

__global__ void __launch_bounds__(512, 1) k2_attn(
    const int* __restrict__ adj, float* __restrict__ out)
{
    extern __shared__ __align__(16) char smRaw[];
    __shared__ float s1S[128];
    __shared__ __align__(16) float s2S[N_];
    __shared__ float rsS[128][4];
    __shared__ float rInv[128];

    const int t    = threadIdx.x;
    const int lane = t & 31;
    const int wid  = t >> 5;
    const int wm   = wid & 3;
    const int wn   = wid >> 2;
    const int b    = blockIdx.x >> 4;
    const int i0   = (blockIdx.x & 15) * 128;

    const uint32_t smBase = smem_u32(smRaw);

    if (t < 128) s1S[t] = g_s1[b * N_ + i0 + t];
    {
        const float4* s2g = (const float4*)(g_s2 + b * N_);
#pragma unroll
        for (int k = t; k < N_ / 4; k += 512) ((float4*)s2S)[k] = s2g[k];
    }

    const int ig = t >> 2;
    const int jg = (t & 3) * 8;
    const int fB = t >> 1;
    const int hB = (t & 1) * 16;

    const int* adjP = adj + (size_t)(b * N_ + i0 + ig) * N_;
    const __nv_bfloat16* bhP = g_WhT_hi + (size_t)(b * F_ + fB) * N_;
    const __nv_bfloat16* blP = g_WhT_lo + (size_t)(b * F_ + fB) * N_;

    float acc[2][8][4];
#pragma unroll
    for (int m = 0; m < 2; m++)
#pragma unroll
        for (int n = 0; n < 8; n++)
#pragma unroll
            for (int q = 0; q < 4; q++) acc[m][n][q] = 0.f;
    float lsum = 0.f;

    uint32_t hw[4], lw[4];

    __syncthreads();

    {
        int4 a0 = *(const int4*)(adjP + jg);
        int4 a1 = *(const int4*)(adjP + jg + 4);
        const float s1v = s1S[ig];
        make_w_pair(s1v, a0.x, a0.y, s2S[jg + 0], s2S[jg + 1], lsum, hw[0], lw[0]);
        make_w_pair(s1v, a0.z, a0.w, s2S[jg + 2], s2S[jg + 3], lsum, hw[1], lw[1]);
        make_w_pair(s1v, a1.x, a1.y, s2S[jg + 4], s2S[jg + 5], lsum, hw[2], lw[2]);
        make_w_pair(s1v, a1.z, a1.w, s2S[jg + 6], s2S[jg + 7], lsum, hw[3], lw[3]);

        uint32_t dH = smBase + 2 * A_BYTES + (uint32_t)(fB * BST + hB) * 2u;
        cp_async16(dH,      bhP + hB);
        cp_async16(dH + 16, bhP + hB + 8);
        cp_async16(dH + B_BYTES,      blP + hB);
        cp_async16(dH + B_BYTES + 16, blP + hB + 8);
        CP_COMMIT();

        uint32_t off = (uint32_t)(ig * AST + jg) * 2u;
        asm volatile("st.shared.v4.b32 [%0], {%1,%2,%3,%4};"
                     :: "r"(smBase + off), "r"(hw[0]), "r"(hw[1]), "r"(hw[2]), "r"(hw[3]));
        asm volatile("st.shared.v4.b32 [%0], {%1,%2,%3,%4};"
                     :: "r"(smBase + A_BYTES + off), "r"(lw[0]), "r"(lw[1]), "r"(lw[2]), "r"(lw[3]));
        CP_WAIT0();
    }
    __syncthreads();

    for (int c = 0; c < NCH2; ++c) {
        const uint32_t sb   = smBase + (c & 1) * STAGE;
        const uint32_t sbN  = smBase + ((c + 1) & 1) * STAGE;
        const uint32_t aHiS = sb;
        const uint32_t aLoS = sb + A_BYTES;
        const uint32_t bHiS = sb + 2 * A_BYTES;
        const uint32_t bLoS = bHiS + B_BYTES;
        const bool doNext = (c + 1 < NCH2);
        const int  jn = (c + 1) * KC2;

        int4 pA0, pA1;
        if (doNext) {
            uint32_t dH = sbN + 2 * A_BYTES + (uint32_t)(fB * BST + hB) * 2u;
            cp_async16(dH,      bhP + jn + hB);
            cp_async16(dH + 16, bhP + jn + hB + 8);
            cp_async16(dH + B_BYTES,      blP + jn + hB);
            cp_async16(dH + B_BYTES + 16, blP + jn + hB + 8);
            CP_COMMIT();
            pA0 = *(const int4*)(adjP + jn + jg);
            pA1 = *(const int4*)(adjP + jn + jg + 4);
        }
        const float s1v = s1S[ig];

#pragma unroll
        for (int ks = 0; ks < 2; ++ks) {
            const int k0 = ks * 16;
            uint32_t ah[2][4], al[2][4];
#pragma unroll
            for (int mt = 0; mt < 2; ++mt) {
                int arow = wm * 32 + mt * 16 + (lane & 15);
                uint32_t aoff = (uint32_t)(arow * AST + k0 + ((lane >> 4) << 3)) * 2u;
                ldm_x4(ah[mt][0], ah[mt][1], ah[mt][2], ah[mt][3], aHiS + aoff);
                ldm_x4(al[mt][0], al[mt][1], al[mt][2], al[mt][3], aLoS + aoff);
            }
#pragma unroll
            for (int pr = 0; pr < 4; ++pr) {
                int n0   = wn * 64 + pr * 16;
                int rowB = n0 + (lane & 7) + ((lane >> 4) << 3);
                int colB = k0 + (((lane >> 3) & 1) << 3);
                uint32_t boff = (uint32_t)(rowB * BST + colB) * 2u;
                uint32_t bh0, bh1, bh2, bh3, bl0, bl1, bl2, bl3;
                ldm_x4(bh0, bh1, bh2, bh3, bHiS + boff);
                ldm_x4(bl0, bl1, bl2, bl3, bLoS + boff);
                mma_bf16(acc[0][pr * 2],     ah[0], bh0, bh1);
                mma_bf16(acc[1][pr * 2],     ah[1], bh0, bh1);
                mma_bf16(acc[0][pr * 2 + 1], ah[0], bh2, bh3);
                mma_bf16(acc[1][pr * 2 + 1], ah[1], bh2, bh3);
                mma_bf16(acc[0][pr * 2],     ah[0], bl0, bl1);
                mma_bf16(acc[1][pr * 2],     ah[1], bl0, bl1);
                mma_bf16(acc[0][pr * 2 + 1], ah[0], bl2, bl3);
                mma_bf16(acc[1][pr * 2 + 1], ah[1], bl2, bl3);
                mma_bf16(acc[0][pr * 2],     al[0], bh0, bh1);
                mma_bf16(acc[1][pr * 2],     al[1], bh0, bh1);
                mma_bf16(acc[0][pr * 2 + 1], al[0], bh2, bh3);
                mma_bf16(acc[1][pr * 2 + 1], al[1], bh2, bh3);

                if (doNext && ks == 1) {
                    int a0 = (pr < 2) ? ((pr == 0) ? pA0.x : pA0.z)
                                      : ((pr == 2) ? pA1.x : pA1.z);
                    int a1 = (pr < 2) ? ((pr == 0) ? pA0.y : pA0.w)
                                      : ((pr == 2) ? pA1.y : pA1.w);
                    make_w_pair(s1v, a0, a1,
                                s2S[jn + jg + 2 * pr], s2S[jn + jg + 2 * pr + 1],
                                lsum, hw[pr], lw[pr]);
                }
            }
        }

        if (doNext) {
            uint32_t off = (uint32_t)(ig * AST + jg) * 2u;
            asm volatile("st.shared.v4.b32 [%0], {%1,%2,%3,%4};"
                         :: "r"(sbN + off), "r"(hw[0]), "r"(hw[1]), "r"(hw[2]), "r"(hw[3]));
            asm volatile("st.shared.v4.b32 [%0], {%1,%2,%3,%4};"
                         :: "r"(sbN + A_BYTES + off), "r"(lw[0]), "r"(lw[1]), "r"(lw[2]), "r"(lw[3]));
            CP_WAIT0();
        }
        __syncthreads();
    }

    rsS[ig][t & 3] = lsum;
    __syncthreads();
    if (t < 128) rInv[t] = 1.f / (rsS[t][0] + rsS[t][1] + rsS[t][2] + rsS[t][3]);
    __syncthreads();

    const int g  = lane >> 2;
    const int tq = lane & 3;
#pragma unroll
    for (int mt = 0; mt < 2; ++mt) {
        int r0l = wm * 32 + mt * 16 + g;
        int r1l = r0l + 8;
        float inv0 = rInv[r0l], inv1 = rInv[r1l];
        size_t o0 = ((size_t)(b * N_ + i0 + r0l)) * F_;
        size_t o1 = ((size_t)(b * N_ + i0 + r1l)) * F_;
#pragma unroll
        for (int nt = 0; nt < 8; ++nt) {
            int col = wn * 64 + nt * 8 + 2 * tq;
            float x0 = acc[mt][nt][0] * inv0;
            float x1 = acc[mt][nt][1] * inv0;
            float x2 = acc[mt][nt][2] * inv1;
            float x3 = acc[mt][nt][3] * inv1;
            x0 = (x0 > 0.f) ? x0 : expm1f(x0);
            x1 = (x1 > 0.f) ? x1 : expm1f(x1);
            x2 = (x2 > 0.f) ? x2 : expm1f(x2);
            x3 = (x3 > 0.f) ? x3 : expm1f(x3);
            *(float2*)(out + o0 + col) = make_float2(x0, x1);
            *(float2*)(out + o1 + col) = make_float2(x2, x3);
        }
    }
}

// ---------------------------------------------------------------------------
extern "C" void kernel_launch(void* const* d_in, const int* in_sizes, int n_in,
                              void* d_out, int out_size)
{
    const float* h   = (const float*)d_in[0];
    const int*   adj = (const int*)  d_in[1];
    const float* Ww  = (const float*)d_in[2];
    const float* Wb  = (const float*)d_in[3];
    const float* aiw = (const float*)d_in[4];
    const float* aib = (const float*)d_in[5];
    const float* ajw = (const float*)d_in[6];
    const float* ajb = (const float*)d_in[7];
    float* out = (float*)d_out;

    static bool attrDone = false;
    if (!attrDone) {
        cudaFuncSetAttribute(k1_hmma, cudaFuncAttributeMaxDynamicSharedMemorySize,
                             DYN_SMEM);
        cudaFuncSetAttribute(k2_attn, cudaFuncAttributeMaxDynamicSharedMemorySize,
                             DYN_SMEM);
        attrDone = true;
    }

    k0_convW<<<32, 256>>>(Ww);
    k1_hmma<<<(B_ * N_) / 128, 512, DYN_SMEM>>>(h, Wb, aiw, aib, ajw, ajb);
    k2_attn<<<B_ * (N_ / 128), 512, DYN_SMEM>>>(adj, out);
}

// round 12
// speedup vs baseline: 1.6020x; 1.0058x over previous
#include <cuda_runtime.h>
#include <cuda_bf16.h>
#include <math.h>
#include <cstdint>
#include <cstddef>

#define B_   8
#define N_   2048
#define F_   256
#define ALPHA 0.2f

// ---------------- device scratch (allocation-free rule) ----------------
__device__ float g_s1[B_ * N_];
__device__ float g_s2[B_ * N_];
__device__ __nv_bfloat16 g_WhT_hi[B_ * F_ * N_];   // [b][f][j]
__device__ __nv_bfloat16 g_WhT_lo[B_ * F_ * N_];
__device__ __nv_bfloat16 gW_hi[F_ * F_];           // W split, [out][k]
__device__ __nv_bfloat16 gW_lo[F_ * F_];

__device__ __forceinline__ uint32_t smem_u32(const void* p) {
    uint32_t a;
    asm("{ .reg .u64 t; cvta.to.shared.u64 t, %1; cvt.u32.u64 %0, t; }"
        : "=r"(a) : "l"(p));
    return a;
}
__device__ __forceinline__ void ldm_x4(uint32_t& r0, uint32_t& r1,
                                       uint32_t& r2, uint32_t& r3, uint32_t addr) {
    asm volatile("ldmatrix.sync.aligned.m8n8.x4.shared.b16 {%0,%1,%2,%3}, [%4];"
                 : "=r"(r0), "=r"(r1), "=r"(r2), "=r"(r3) : "r"(addr));
}
__device__ __forceinline__ void mma_bf16(float* d, const uint32_t* a,
                                         uint32_t b0, uint32_t b1) {
    asm volatile(
        "mma.sync.aligned.m16n8k16.row.col.f32.bf16.bf16.f32 "
        "{%0,%1,%2,%3}, {%4,%5,%6,%7}, {%8,%9}, {%0,%1,%2,%3};"
        : "+f"(d[0]), "+f"(d[1]), "+f"(d[2]), "+f"(d[3])
        : "r"(a[0]), "r"(a[1]), "r"(a[2]), "r"(a[3]), "r"(b0), "r"(b1));
}
__device__ __forceinline__ void cp_async16(uint32_t dst, const void* src) {
    asm volatile("cp.async.cg.shared.global [%0], [%1], 16;"
                 :: "r"(dst), "l"(src) : "memory");
}
#define CP_COMMIT() asm volatile("cp.async.commit_group;" ::: "memory")
#define CP_WAIT0()  asm volatile("cp.async.wait_group 0;" ::: "memory")

__device__ __forceinline__ void split_pair(float v0, float v1,
                                           uint32_t& hiP, uint32_t& loP) {
    __nv_bfloat16 h0 = __float2bfloat16(v0), h1 = __float2bfloat16(v1);
    float r0 = v0 - __bfloat162float(h0);
    float r1 = v1 - __bfloat162float(h1);
    __nv_bfloat16 l0 = __float2bfloat16(r0), l1 = __float2bfloat16(r1);
    __nv_bfloat162 hp = __halves2bfloat162(h0, h1);
    __nv_bfloat162 lp = __halves2bfloat162(l0, l1);
    hiP = *(uint32_t*)&hp;
    loP = *(uint32_t*)&lp;
}

// w-pair: leaky+exp+mask, bf16 hi/lo split, rowsum accumulate
__device__ __forceinline__ void make_w_pair(float s1v, int a0, int a1,
                                            float s20, float s21,
                                            float& lsum, uint32_t& hiP, uint32_t& loP)
{
    float x0 = s1v + s20; x0 = fmaxf(x0, ALPHA * x0);
    float x1 = s1v + s21; x1 = fmaxf(x1, ALPHA * x1);
    float w0 = (a0 > 0) ? __expf(x0) : 0.f;
    float w1 = (a1 > 0) ? __expf(x1) : 0.f;
    lsum += w0 + w1;
    split_pair(w0, w1, hiP, loP);
}

// ---------------------------------------------------------------------------
// Kernel 0: split W (256x256 fp32, [out][k]) into bf16 hi/lo.
//   Grid 128 x 256, one pair per thread (latency-optimized; old grid=32 was
//   MLP-starved at 4.3us).
// ---------------------------------------------------------------------------
__global__ void __launch_bounds__(256) k0_convW(const float* __restrict__ Ww)
{
    int idx = (blockIdx.x * 256 + threadIdx.x) * 2;
    float2 v = *(const float2*)(Ww + idx);
    uint32_t hw, lw;
    split_pair(v.x, v.y, hw, lw);
    *(uint32_t*)(gW_hi + idx) = hw;
    *(uint32_t*)(gW_lo + idx) = lw;
}

// ---------------------------------------------------------------------------
// Shared tile constants (k1_hmma and k2 use the same skeleton)
// ---------------------------------------------------------------------------
#define KC2   32
#define AST   40
#define BST   40
#define A_BYTES (128 * AST * 2)           // 10240
#define B_BYTES (256 * BST * 2)           // 20480
#define STAGE   (2 * A_BYTES + 2 * B_BYTES)   // 61440
#define DYN_SMEM (2 * STAGE)                  // 122880

// ---------------------------------------------------------------------------
// Kernel 1: HMMA Wh = h @ W^T (+bias, s1/s2), bf16 3-term split.
//   CTA 128 rows x 256 out, 512 thr, 8 k-chunks of 32.
//   FUSED epilogue: stages the output tile in smem (2 x 128f passes) and
//   writes WhT hi/lo directly (transpose+split) — no g_Wh round-trip.
// ---------------------------------------------------------------------------
__global__ void __launch_bounds__(512, 1) k1_hmma(
    const float* __restrict__ h,  const float* __restrict__ Wb,
    const float* __restrict__ aiw, const float* __restrict__ aib,
    const float* __restrict__ ajw, const float* __restrict__ ajb)
{
    extern __shared__ __align__(16) char smRaw[];
    __shared__ float sWb[F_], sAi[F_], sAj[F_];
    __shared__ float red1[128][4], red2[128][4];

    const int t    = threadIdx.x;
    const int lane = t & 31;
    const int wid  = t >> 5;
    const int wm   = wid & 3;
    const int wn   = wid >> 2;
    const int row0 = blockIdx.x * 128;

    const uint32_t smBase = smem_u32(smRaw);

    if (t < F_) { sWb[t] = Wb[t]; sAi[t] = aiw[t]; sAj[t] = ajw[t]; }

    // ---- roles (identical to k2) ----
    const int ig = t >> 2;                   // A row 0..127
    const int jg = (t & 3) * 8;              // 8-k subgroup
    const int fB = t >> 1;                   // B row (out) 0..255
    const int hB = (t & 1) * 16;

    const float* hP = h + (size_t)(row0 + ig) * F_;
    const __nv_bfloat16* wHiP = gW_hi + fB * F_;
    const __nv_bfloat16* wLoP = gW_lo + fB * F_;

    float acc[2][8][4];
#pragma unroll
    for (int m = 0; m < 2; m++)
#pragma unroll
        for (int n = 0; n < 8; n++)
#pragma unroll
            for (int q = 0; q < 4; q++) acc[m][n][q] = 0.f;

    uint32_t hw[4], lw[4];

    // ---- prologue: A(0) from h, B(0) via cp.async ----
    {
        float4 v0 = *(const float4*)(hP + jg);
        float4 v1 = *(const float4*)(hP + jg + 4);
        split_pair(v0.x, v0.y, hw[0], lw[0]);
        split_pair(v0.z, v0.w, hw[1], lw[1]);
        split_pair(v1.x, v1.y, hw[2], lw[2]);
        split_pair(v1.z, v1.w, hw[3], lw[3]);

        uint32_t dH = smBase + 2 * A_BYTES + (uint32_t)(fB * BST + hB) * 2u;
        cp_async16(dH,      wHiP + hB);
        cp_async16(dH + 16, wHiP + hB + 8);
        cp_async16(dH + B_BYTES,      wLoP + hB);
        cp_async16(dH + B_BYTES + 16, wLoP + hB + 8);
        CP_COMMIT();

        uint32_t off = (uint32_t)(ig * AST + jg) * 2u;
        asm volatile("st.shared.v4.b32 [%0], {%1,%2,%3,%4};"
                     :: "r"(smBase + off), "r"(hw[0]), "r"(hw[1]), "r"(hw[2]), "r"(hw[3]));
        asm volatile("st.shared.v4.b32 [%0], {%1,%2,%3,%4};"
                     :: "r"(smBase + A_BYTES + off), "r"(lw[0]), "r"(lw[1]), "r"(lw[2]), "r"(lw[3]));
        CP_WAIT0();
    }
    __syncthreads();

    for (int c = 0; c < 8; ++c) {
        const uint32_t sb   = smBase + (c & 1) * STAGE;
        const uint32_t sbN  = smBase + ((c + 1) & 1) * STAGE;
        const uint32_t aHiS = sb;
        const uint32_t aLoS = sb + A_BYTES;
        const uint32_t bHiS = sb + 2 * A_BYTES;
        const uint32_t bLoS = bHiS + B_BYTES;
        const bool doNext = (c + 1 < 8);
        const int  kn = (c + 1) * KC2;

        float4 ph0, ph1;
        if (doNext) {
            uint32_t dH = sbN + 2 * A_BYTES + (uint32_t)(fB * BST + hB) * 2u;
            cp_async16(dH,      wHiP + kn + hB);
            cp_async16(dH + 16, wHiP + kn + hB + 8);
            cp_async16(dH + B_BYTES,      wLoP + kn + hB);
            cp_async16(dH + B_BYTES + 16, wLoP + kn + hB + 8);
            CP_COMMIT();
            ph0 = *(const float4*)(hP + kn + jg);
            ph1 = *(const float4*)(hP + kn + jg + 4);
        }

        // ---- MMA(c) ----
#pragma unroll
        for (int ks = 0; ks < 2; ++ks) {
            const int k0 = ks * 16;
            uint32_t ah[2][4], al[2][4];
#pragma unroll
            for (int mt = 0; mt < 2; ++mt) {
                int arow = wm * 32 + mt * 16 + (lane & 15);
                uint32_t aoff = (uint32_t)(arow * AST + k0 + ((lane >> 4) << 3)) * 2u;
                ldm_x4(ah[mt][0], ah[mt][1], ah[mt][2], ah[mt][3], aHiS + aoff);
                ldm_x4(al[mt][0], al[mt][1], al[mt][2], al[mt][3], aLoS + aoff);
            }
#pragma unroll
            for (int pr = 0; pr < 4; ++pr) {
                int n0   = wn * 64 + pr * 16;
                int rowB = n0 + (lane & 7) + ((lane >> 4) << 3);
                int colB = k0 + (((lane >> 3) & 1) << 3);
                uint32_t boff = (uint32_t)(rowB * BST + colB) * 2u;
                uint32_t bh0, bh1, bh2, bh3, bl0, bl1, bl2, bl3;
                ldm_x4(bh0, bh1, bh2, bh3, bHiS + boff);
                ldm_x4(bl0, bl1, bl2, bl3, bLoS + boff);
                mma_bf16(acc[0][pr * 2],     ah[0], bh0, bh1);
                mma_bf16(acc[1][pr * 2],     ah[1], bh0, bh1);
                mma_bf16(acc[0][pr * 2 + 1], ah[0], bh2, bh3);
                mma_bf16(acc[1][pr * 2 + 1], ah[1], bh2, bh3);
                mma_bf16(acc[0][pr * 2],     ah[0], bl0, bl1);
                mma_bf16(acc[1][pr * 2],     ah[1], bl0, bl1);
                mma_bf16(acc[0][pr * 2 + 1], ah[0], bl2, bl3);
                mma_bf16(acc[1][pr * 2 + 1], ah[1], bl2, bl3);
                mma_bf16(acc[0][pr * 2],     al[0], bh0, bh1);
                mma_bf16(acc[1][pr * 2],     al[1], bh0, bh1);
                mma_bf16(acc[0][pr * 2 + 1], al[0], bh2, bh3);
                mma_bf16(acc[1][pr * 2 + 1], al[1], bh2, bh3);
            }
        }

        if (doNext) {
            split_pair(ph0.x, ph0.y, hw[0], lw[0]);
            split_pair(ph0.z, ph0.w, hw[1], lw[1]);
            split_pair(ph1.x, ph1.y, hw[2], lw[2]);
            split_pair(ph1.z, ph1.w, hw[3], lw[3]);
            uint32_t off = (uint32_t)(ig * AST + jg) * 2u;
            asm volatile("st.shared.v4.b32 [%0], {%1,%2,%3,%4};"
                         :: "r"(sbN + off), "r"(hw[0]), "r"(hw[1]), "r"(hw[2]), "r"(hw[3]));
            asm volatile("st.shared.v4.b32 [%0], {%1,%2,%3,%4};"
                         :: "r"(sbN + A_BYTES + off), "r"(lw[0]), "r"(lw[1]), "r"(lw[2]), "r"(lw[3]));
            CP_WAIT0();
        }
        __syncthreads();
    }

    // ---- epilogue part 1: bias, s1/s2 reduction ----
    const int g  = lane >> 2;
    const int tq = lane & 3;
#pragma unroll
    for (int mt = 0; mt < 2; ++mt) {
        int r0l = wm * 32 + mt * 16 + g;
        int r1l = r0l + 8;
        float a1_0 = 0.f, a2_0 = 0.f, a1_1 = 0.f, a2_1 = 0.f;
#pragma unroll
        for (int nt = 0; nt < 8; ++nt) {
            int col = wn * 64 + nt * 8 + 2 * tq;
            float b0 = sWb[col], b1 = sWb[col + 1];
            float i0v = sAi[col], i1v = sAi[col + 1];
            float j0v = sAj[col], j1v = sAj[col + 1];
            acc[mt][nt][0] += b0; acc[mt][nt][1] += b1;
            acc[mt][nt][2] += b0; acc[mt][nt][3] += b1;
            a1_0 = fmaf(acc[mt][nt][0], i0v, fmaf(acc[mt][nt][1], i1v, a1_0));
            a2_0 = fmaf(acc[mt][nt][0], j0v, fmaf(acc[mt][nt][1], j1v, a2_0));
            a1_1 = fmaf(acc[mt][nt][2], i0v, fmaf(acc[mt][nt][3], i1v, a1_1));
            a2_1 = fmaf(acc[mt][nt][2], j0v, fmaf(acc[mt][nt][3], j1v, a2_1));
        }
#pragma unroll
        for (int off = 1; off <= 2; off <<= 1) {
            a1_0 += __shfl_xor_sync(0xffffffffu, a1_0, off);
            a2_0 += __shfl_xor_sync(0xffffffffu, a2_0, off);
            a1_1 += __shfl_xor_sync(0xffffffffu, a1_1, off);
            a2_1 += __shfl_xor_sync(0xffffffffu, a2_1, off);
        }
        if (tq == 0) {
            red1[r0l][wn] = a1_0; red2[r0l][wn] = a2_0;
            red1[r1l][wn] = a1_1; red2[r1l][wn] = a2_1;
        }
    }
    __syncthreads();
    if (t < 128) {
        g_s1[row0 + t] = red1[t][0] + red1[t][1] + red1[t][2] + red1[t][3] + aib[0];
        g_s2[row0 + t] = red2[t][0] + red2[t][1] + red2[t][2] + red2[t][3] + ajb[0];
    }

    // ---- epilogue part 2: FUSED transpose + bf16 split, two 128f passes ----
    float* ts = (float*)smRaw;
    const int b   = row0 >> 11;
    const int jlo = row0 & (N_ - 1);
    const int fLoc = t >> 2;                 // 0..127
    const int jseg = (t & 3) * 32;           // 0,32,64,96

#pragma unroll
    for (int fh = 0; fh < 2; ++fh) {
        __syncthreads();
        if ((wn >> 1) == fh) {
#pragma unroll
            for (int mt = 0; mt < 2; ++mt) {
                int r0l = wm * 32 + mt * 16 + g;
                int r1l = r0l + 8;
#pragma unroll
                for (int nt = 0; nt < 8; ++nt) {
                    int colL = (wn & 1) * 64 + nt * 8 + 2 * tq;
                    *(float2*)&ts[r0l * 132 + colL] =
                        make_float2(acc[mt][nt][0], acc[mt][nt][1]);
                    *(float2*)&ts[r1l * 132 + colL] =
                        make_float2(acc[mt][nt][2], acc[mt][nt][3]);
                }
            }
        }
        __syncthreads();
        uint32_t hp[16], lp[16];
#pragma unroll
        for (int e = 0; e < 32; e += 2) {
            float v0 = ts[(jseg + e) * 132 + fLoc];
            float v1 = ts[(jseg + e + 1) * 132 + fLoc];
            split_pair(v0, v1, hp[e >> 1], lp[e >> 1]);
        }
        size_t dst = ((size_t)(b * F_ + fh * 128 + fLoc)) * N_ + jlo + jseg;
        uint4* dh = (uint4*)(g_WhT_hi + dst);
        uint4* dl = (uint4*)(g_WhT_lo + dst);
        dh[0] = make_uint4(hp[0],  hp[1],  hp[2],  hp[3]);
        dh[1] = make_uint4(hp[4],  hp[5],  hp[6],  hp[7]);
        dh[2] = make_uint4(hp[8],  hp[9],  hp[10], hp[11]);
        dh[3] = make_uint4(hp[12], hp[13], hp[14], hp[15]);
        dl[0] = make_uint4(lp[0],  lp[1],  lp[2],  lp[3]);
        dl[1] = make_uint4(lp[4],  lp[5],  lp[6],  lp[7]);
        dl[2] = make_uint4(lp[8],  lp[9],  lp[10], lp[11]);
        dl[3] = make_uint4(lp[12], lp[13], lp[14], lp[15]);
    }
}

// ---------------------------------------------------------------------------
// Kernel 2: HMMA attention GEMM (R7/R10 best: 512 thr, 128i x 256f)
// ---------------------------------------------------------------------------
#define NCH2  (N_ / KC2)                  // 64 chunks

__global__ void __launch_bounds__(512, 1) k2_attn(
    const int* __restrict__ adj, float* __restrict__ out)
{
    extern __shared__ __align__(16) char smRaw[];
    __shared__ float s1S[128];
    __shared__ __align__(16) float s2S[N_];
    __shared__ float rsS[128][4];
    __shared__ float rInv[128];

    const int t    = threadIdx.x;
    const int lane = t & 31;
    const int wid  = t >> 5;
    const int wm   = wid & 3;
    const int wn   = wid >> 2;
    const int b    = blockIdx.x >> 4;
    const int i0   = (blockIdx.x & 15) * 128;

    const uint32_t smBase = smem_u32(smRaw);

    if (t < 128) s1S[t] = g_s1[b * N_ + i0 + t];
    {
        const float4* s2g = (const float4*)(g_s2 + b * N_);
#pragma unroll
        for (int k = t; k < N_ / 4; k += 512) ((float4*)s2S)[k] = s2g[k];
    }

    const int ig = t >> 2;
    const int jg = (t & 3) * 8;
    const int fB = t >> 1;
    const int hB = (t & 1) * 16;

    const int* adjP = adj + (size_t)(b * N_ + i0 + ig) * N_;
    const __nv_bfloat16* bhP = g_WhT_hi + (size_t)(b * F_ + fB) * N_;
    const __nv_bfloat16* blP = g_WhT_lo + (size_t)(b * F_ + fB) * N_;

    float acc[2][8][4];
#pragma unroll
    for (int m = 0; m < 2; m++)
#pragma unroll
        for (int n = 0; n < 8; n++)
#pragma unroll
            for (int q = 0; q < 4; q++) acc[m][n][q] = 0.f;
    float lsum = 0.f;

    uint32_t hw[4], lw[4];

    __syncthreads();

    {
        int4 a0 = *(const int4*)(adjP + jg);
        int4 a1 = *(const int4*)(adjP + jg + 4);
        const float s1v = s1S[ig];
        make_w_pair(s1v, a0.x, a0.y, s2S[jg + 0], s2S[jg + 1], lsum, hw[0], lw[0]);
        make_w_pair(s1v, a0.z, a0.w, s2S[jg + 2], s2S[jg + 3], lsum, hw[1], lw[1]);
        make_w_pair(s1v, a1.x, a1.y, s2S[jg + 4], s2S[jg + 5], lsum, hw[2], lw[2]);
        make_w_pair(s1v, a1.z, a1.w, s2S[jg + 6], s2S[jg + 7], lsum, hw[3], lw[3]);

        uint32_t dH = smBase + 2 * A_BYTES + (uint32_t)(fB * BST + hB) * 2u;
        cp_async16(dH,      bhP + hB);
        cp_async16(dH + 16, bhP + hB + 8);
        cp_async16(dH + B_BYTES,      blP + hB);
        cp_async16(dH + B_BYTES + 16, blP + hB + 8);
        CP_COMMIT();

        uint32_t off = (uint32_t)(ig * AST + jg) * 2u;
        asm volatile("st.shared.v4.b32 [%0], {%1,%2,%3,%4};"
                     :: "r"(smBase + off), "r"(hw[0]), "r"(hw[1]), "r"(hw[2]), "r"(hw[3]));
        asm volatile("st.shared.v4.b32 [%0], {%1,%2,%3,%4};"
                     :: "r"(smBase + A_BYTES + off), "r"(lw[0]), "r"(lw[1]), "r"(lw[2]), "r"(lw[3]));
        CP_WAIT0();
    }
    __syncthreads();

    for (int c = 0; c < NCH2; ++c) {
        const uint32_t sb   = smBase + (c & 1) * STAGE;
        const uint32_t sbN  = smBase + ((c + 1) & 1) * STAGE;
        const uint32_t aHiS = sb;
        const uint32_t aLoS = sb + A_BYTES;
        const uint32_t bHiS = sb + 2 * A_BYTES;
        const uint32_t bLoS = bHiS + B_BYTES;
        const bool doNext = (c + 1 < NCH2);
        const int  jn = (c + 1) * KC2;

        int4 pA0, pA1;
        if (doNext) {
            uint32_t dH = sbN + 2 * A_BYTES + (uint32_t)(fB * BST + hB) * 2u;
            cp_async16(dH,      bhP + jn + hB);
            cp_async16(dH + 16, bhP + jn + hB + 8);
            cp_async16(dH + B_BYTES,      blP + jn + hB);
            cp_async16(dH + B_BYTES + 16, blP + jn + hB + 8);
            CP_COMMIT();
            pA0 = *(const int4*)(adjP + jn + jg);
            pA1 = *(const int4*)(adjP + jn + jg + 4);
        }
        const float s1v = s1S[ig];

#pragma unroll
        for (int ks = 0; ks < 2; ++ks) {
            const int k0 = ks * 16;
            uint32_t ah[2][4], al[2][4];
#pragma unroll
            for (int mt = 0; mt < 2; ++mt) {
                int arow = wm * 32 + mt * 16 + (lane & 15);
                uint32_t aoff = (uint32_t)(arow * AST + k0 + ((lane >> 4) << 3)) * 2u;
                ldm_x4(ah[mt][0], ah[mt][1], ah[mt][2], ah[mt][3], aHiS + aoff);
                ldm_x4(al[mt][0], al[mt][1], al[mt][2], al[mt][3], aLoS + aoff);
            }
#pragma unroll
            for (int pr = 0; pr < 4; ++pr) {
                int n0   = wn * 64 + pr * 16;
                int rowB = n0 + (lane & 7) + ((lane >> 4) << 3);
                int colB = k0 + (((lane >> 3) & 1) << 3);
                uint32_t boff = (uint32_t)(rowB * BST + colB) * 2u;
                uint32_t bh0, bh1, bh2, bh3, bl0, bl1, bl2, bl3;
                ldm_x4(bh0, bh1, bh2, bh3, bHiS + boff);
                ldm_x4(bl0, bl1, bl2, bl3, bLoS + boff);
                mma_bf16(acc[0][pr * 2],     ah[0], bh0, bh1);
                mma_bf16(acc[1][pr * 2],     ah[1], bh0, bh1);
                mma_bf16(acc[0][pr * 2 + 1], ah[0], bh2, bh3);
                mma_bf16(acc[1][pr * 2 + 1], ah[1], bh2, bh3);
                mma_bf16(acc[0][pr * 2],     ah[0], bl0, bl1);
                mma_bf16(acc[1][pr * 2],     ah[1], bl0, bl1);
                mma_bf16(acc[0][pr * 2 + 1], ah[0], bl2, bl3);
                mma_bf16(acc[1][pr * 2 + 1], ah[1], bl2, bl3);
                mma_bf16(acc[0][pr * 2],     al[0], bh0, bh1);
                mma_bf16(acc[1][pr * 2],     al[1], bh0, bh1);
                mma_bf16(acc[0][pr * 2 + 1], al[0], bh2, bh3);
                mma_bf16(acc[1][pr * 2 + 1], al[1], bh2, bh3);

                if (doNext && ks == 1) {
                    int a0 = (pr < 2) ? ((pr == 0) ? pA0.x : pA0.z)
                                      : ((pr == 2) ? pA1.x : pA1.z);
                    int a1 = (pr < 2) ? ((pr == 0) ? pA0.y : pA0.w)
                                      : ((pr == 2) ? pA1.y : pA1.w);
                    make_w_pair(s1v, a0, a1,
                                s2S[jn + jg + 2 * pr], s2S[jn + jg + 2 * pr + 1],
                                lsum, hw[pr], lw[pr]);
                }
            }
        }

        if (doNext) {
            uint32_t off = (uint32_t)(ig * AST + jg) * 2u;
            asm volatile("st.shared.v4.b32 [%0], {%1,%2,%3,%4};"
                         :: "r"(sbN + off), "r"(hw[0]), "r"(hw[1]), "r"(hw[2]), "r"(hw[3]));
            asm volatile("st.shared.v4.b32 [%0], {%1,%2,%3,%4};"
                         :: "r"(sbN + A_BYTES + off), "r"(lw[0]), "r"(lw[1]), "r"(lw[2]), "r"(lw[3]));
            CP_WAIT0();
        }
        __syncthreads();
    }

    rsS[ig][t & 3] = lsum;
    __syncthreads();
    if (t < 128) rInv[t] = 1.f / (rsS[t][0] + rsS[t][1] + rsS[t][2] + rsS[t][3]);
    __syncthreads();

    const int g  = lane >> 2;
    const int tq = lane & 3;
#pragma unroll
    for (int mt = 0; mt < 2; ++mt) {
        int r0l = wm * 32 + mt * 16 + g;
        int r1l = r0l + 8;
        float inv0 = rInv[r0l], inv1 = rInv[r1l];
        size_t o0 = ((size_t)(b * N_ + i0 + r0l)) * F_;
        size_t o1 = ((size_t)(b * N_ + i0 + r1l)) * F_;
#pragma unroll
        for (int nt = 0; nt < 8; ++nt) {
            int col = wn * 64 + nt * 8 + 2 * tq;
            float x0 = acc[mt][nt][0] * inv0;
            float x1 = acc[mt][nt][1] * inv0;
            float x2 = acc[mt][nt][2] * inv1;
            float x3 = acc[mt][nt][3] * inv1;
            x0 = (x0 > 0.f) ? x0 : expm1f(x0);
            x1 = (x1 > 0.f) ? x1 : expm1f(x1);
            x2 = (x2 > 0.f) ? x2 : expm1f(x2);
            x3 = (x3 > 0.f) ? x3 : expm1f(x3);
            *(float2*)(out + o0 + col) = make_float2(x0, x1);
            *(float2*)(out + o1 + col) = make_float2(x2, x3);
        }
    }
}

// ---------------------------------------------------------------------------
extern "C" void kernel_launch(void* const* d_in, const int* in_sizes, int n_in,
                              void* d_out, int out_size)
{
    const float* h   = (const float*)d_in[0];
    const int*   adj = (const int*)  d_in[1];
    const float* Ww  = (const float*)d_in[2];
    const float* Wb  = (const float*)d_in[3];
    const float* aiw = (const float*)d_in[4];
    const float* aib = (const float*)d_in[5];
    const float* ajw = (const float*)d_in[6];
    const float* ajb = (const float*)d_in[7];
    float* out = (float*)d_out;

    static bool attrDone = false;
    if (!attrDone) {
        cudaFuncSetAttribute(k1_hmma, cudaFuncAttributeMaxDynamicSharedMemorySize,
                             DYN_SMEM);
        cudaFuncSetAttribute(k2_attn, cudaFuncAttributeMaxDynamicSharedMemorySize,
                             DYN_SMEM);
        attrDone = true;
    }

    k0_convW<<<128, 256>>>(Ww);
    k1_hmma<<<(B_ * N_) / 128, 512, DYN_SMEM>>>(h, Wb, aiw, aib, ajw, ajb);
    k2_attn<<<B_ * (N_ / 128), 512, DYN_SMEM>>>(adj, out);
}